// round 14
// baseline (speedup 1.0000x reference)
#include <cuda_runtime.h>
#include <cuda_fp16.h>
#include <math.h>
#include <stdint.h>

#define BB 8
#define SS 1024
#define HID 768
#define NH 12
#define HD 64
#define MROWS (BB*SS)   // 8192
#define MH ((size_t)MROWS*HID)

// ---------------- scratch (device globals; no allocation allowed) ----------------
__device__ __align__(256) __half g_kf [MH];                     // raw key fp16
__device__ __align__(256) __half g_vf [MH];                     // raw value fp16
__device__ __align__(256) __half g_qf [MH];                     // projected Q (fp16, prescaled)
__device__ __align__(256) __half g_kpf[MH];                     // projected K (fp16)
__device__ __align__(256) __half g_vpf[MH];                     // projected V (fp16)

__device__ __align__(256) __half g_xf [MH];
__device__ __align__(256) __half g_cat[2*MH];
__device__ __align__(256) __half g_wqk[(size_t)3*HID*HID];      // Wq,Wk,Wv fp16 [N][K]
__device__ __align__(256) __half g_wfo[(size_t)HID*HID];
__device__ __align__(256) __half g_wf [(size_t)2*2*HID*HID];    // W1,W2 fp16 [N][K]

// ================= helpers =================
__device__ __forceinline__ uint32_t smem_u32(const void* p) {
    uint32_t a;
    asm("{ .reg .u64 t; cvta.to.shared.u64 t, %1; cvt.u32.u64 %0, t; }" : "=r"(a) : "l"(p));
    return a;
}
__device__ __forceinline__ void ldsm_x4(uint32_t* r, uint32_t addr) {
    asm volatile("ldmatrix.sync.aligned.m8n8.x4.shared.b16 {%0,%1,%2,%3}, [%4];"
                 : "=r"(r[0]), "=r"(r[1]), "=r"(r[2]), "=r"(r[3]) : "r"(addr));
}
__device__ __forceinline__ void ldsm_x4_t(uint32_t* r, uint32_t addr) {
    asm volatile("ldmatrix.sync.aligned.m8n8.x4.trans.shared.b16 {%0,%1,%2,%3}, [%4];"
                 : "=r"(r[0]), "=r"(r[1]), "=r"(r[2]), "=r"(r[3]) : "r"(addr));
}
__device__ __forceinline__ void mma16816h(float* c, const uint32_t* a, uint32_t b0, uint32_t b1) {
    asm volatile("mma.sync.aligned.m16n8k16.row.col.f32.f16.f16.f32 "
                 "{%0,%1,%2,%3}, {%4,%5,%6,%7}, {%8,%9}, {%0,%1,%2,%3};"
                 : "+f"(c[0]), "+f"(c[1]), "+f"(c[2]), "+f"(c[3])
                 : "r"(a[0]), "r"(a[1]), "r"(a[2]), "r"(a[3]), "r"(b0), "r"(b1));
}
__device__ __forceinline__ void cp16(uint32_t dst, const void* src) {
    asm volatile("cp.async.cg.shared.global [%0], [%1], 16;" :: "r"(dst), "l"(src));
}
#define CP_COMMIT() asm volatile("cp.async.commit_group;" ::: "memory")
#define CP_WAIT0()  asm volatile("cp.async.wait_group 0;" ::: "memory")

// ================= convert / weight-split kernels =================
__global__ void conv3(const float* __restrict__ q, const float* __restrict__ k,
                      const float* __restrict__ v,
                      __half* __restrict__ cat, __half* __restrict__ kf,
                      __half* __restrict__ vf)
{
    const int z = blockIdx.y;
    const float* src = (z == 0) ? q : (z == 1) ? k : v;
    size_t total = MH / 4;
    for (size_t i = (size_t)blockIdx.x * blockDim.x + threadIdx.x; i < total;
         i += (size_t)gridDim.x * blockDim.x) {
        size_t e = i * 4;
        int m = (int)(e / HID), c = (int)(e % HID);
        float4 x = *(const float4*)(src + e);
        __half* dst = (z == 0) ? (cat + (size_t)m * (2 * HID) + HID + c)
                    : (z == 1) ? (kf + e) : (vf + e);
        *(__half2*)(dst)     = __halves2half2(__float2half(x.x), __float2half(x.y));
        *(__half2*)(dst + 2) = __halves2half2(__float2half(x.z), __float2half(x.w));
    }
}

__global__ void split_wqk3(const float* __restrict__ Wa, const float* __restrict__ Wb,
                           const float* __restrict__ Wc, __half* __restrict__ out)
{
    __shared__ float t[32][33];
    const int z = blockIdx.z;
    const float* W = (z == 0) ? Wa : (z == 1) ? Wb : Wc;
    __half* O = out + (size_t)z * HID * HID;
    int n0 = blockIdx.x * 32, k0 = blockIdx.y * 32;
    int tx = threadIdx.x, ty = threadIdx.y;
    for (int j = ty; j < 32; j += 8)
        t[j][tx] = W[(size_t)(k0 + j) * HID + n0 + tx];
    __syncthreads();
    for (int j = ty; j < 32; j += 8)
        O[(size_t)(n0 + j) * HID + k0 + tx] = __float2half(t[tx][j]);
}

__global__ void split_w_fp16(const float* __restrict__ W, int K, int N,
                             __half* __restrict__ out)
{
    __shared__ float t[32][33];
    int n0 = blockIdx.x * 32, k0 = blockIdx.y * 32;
    int tx = threadIdx.x, ty = threadIdx.y;
    for (int j = ty; j < 32; j += 8)
        t[j][tx] = W[(size_t)(k0 + j) * N + n0 + tx];
    __syncthreads();
    for (int j = ty; j < 32; j += 8)
        out[(size_t)(n0 + j) * K + k0 + tx] = __float2half(t[tx][j]);
}

__global__ void split_wf2(const float* __restrict__ Wa, const float* __restrict__ Wb,
                          __half* __restrict__ out)
{
    __shared__ float t[32][33];
    const int z = blockIdx.z;
    const float* W = (z == 0) ? Wa : Wb;
    __half* O = out + (size_t)z * 2 * HID * HID;
    int n0 = blockIdx.x * 32, k0 = blockIdx.y * 32;
    int tx = threadIdx.x, ty = threadIdx.y;
    for (int j = ty; j < 32; j += 8)
        t[j][tx] = W[(size_t)(k0 + j) * HID + n0 + tx];
    __syncthreads();
    for (int j = ty; j < 32; j += 8)
        O[(size_t)(n0 + j) * (2 * HID) + k0 + tx] = __float2half(t[tx][j]);
}

// ================= fp16 QKV projection GEMM (batched z = 0,1,2) =================
#define GSTRIDE 72
#define GBUF (128 * GSTRIDE)
#define FSTAGE (2 * GBUF)

__global__ __launch_bounds__(256) void gemm_qkv(
    const __half* __restrict__ Aq, const __half* __restrict__ Ak,
    const __half* __restrict__ Av, const __half* __restrict__ Bw,
    const float* __restrict__ bq, const float* __restrict__ bk,
    const float* __restrict__ bv,
    __half* __restrict__ oq, __half* __restrict__ ok, __half* __restrict__ ov)
{
    extern __shared__ __half smh[];
    const int tid = threadIdx.x;
    const int w = tid >> 5, l = tid & 31;
    const int z = blockIdx.z;
    const int m0 = blockIdx.y * 128;
    const int n0 = blockIdx.x * 128;
    const int wm = (w >> 2) * 64;
    const int wn = (w & 3) * 32;

    const __half* A = (z == 0) ? Aq : (z == 1) ? Ak : Av;
    const int lda = (z == 0) ? 2 * HID : HID;
    const __half* B = Bw + (size_t)z * HID * HID;
    const float* bias = (z == 0) ? bq : (z == 1) ? bk : bv;
    const float scale = (z == 0) ? 0.125f : 1.f;
    __half* out = (z == 0) ? oq : (z == 1) ? ok : ov;

    float c[4][4][4];
    #pragma unroll
    for (int i = 0; i < 4; i++)
        #pragma unroll
        for (int j = 0; j < 4; j++)
            #pragma unroll
            for (int q = 0; q < 4; q++) c[i][j][q] = 0.f;

    const uint32_t sbase = smem_u32(smh);
    const int aRow = wm + (l & 15), aKof = (l >> 4) * 8;
    const int bRow = wn + (l >> 4) * 8 + (l & 7), bKof = ((l >> 3) & 1) * 8;
    const int nChunks = HID >> 6;

    auto issue = [&](int ch) {
        const uint32_t dstBase = sbase + (uint32_t)((ch & 1) * FSTAGE * 2);
        const int k0 = ch << 6;
        #pragma unroll
        for (int i = 0; i < 4; i++) {
            int t = tid + i * 256;
            int row = t >> 3, c8 = (t & 7) * 8;
            uint32_t d = dstBase + (uint32_t)((row * GSTRIDE + c8) * 2);
            cp16(d,            A + (size_t)(m0 + row) * lda + k0 + c8);
            cp16(d + GBUF * 2, B + (size_t)(n0 + row) * HID + k0 + c8);
        }
    };

    issue(0); CP_COMMIT();
    for (int ch = 0; ch < nChunks; ch++) {
        CP_WAIT0();
        __syncthreads();
        if (ch + 1 < nChunks) { issue(ch + 1); CP_COMMIT(); }

        const uint32_t sb = sbase + (uint32_t)((ch & 1) * FSTAGE * 2);
        const uint32_t aB = sb + (uint32_t)((aRow * GSTRIDE + aKof) * 2);
        const uint32_t bB = sb + GBUF * 2 + (uint32_t)((bRow * GSTRIDE + bKof) * 2);

        #pragma unroll
        for (int ks = 0; ks < 4; ks++) {
            const uint32_t kb = (uint32_t)(ks * 16 * 2);
            uint32_t ah[4][4], bh[2][4];
            #pragma unroll
            for (int mi = 0; mi < 4; mi++)
                ldsm_x4(ah[mi], aB + (uint32_t)(mi * 16 * GSTRIDE * 2) + kb);
            #pragma unroll
            for (int p = 0; p < 2; p++)
                ldsm_x4(bh[p], bB + (uint32_t)(p * 16 * GSTRIDE * 2) + kb);
            #pragma unroll
            for (int mi = 0; mi < 4; mi++) {
                #pragma unroll
                for (int nj = 0; nj < 4; nj++) {
                    const int p = nj >> 1, s = (nj & 1) * 2;
                    mma16816h(c[mi][nj], ah[mi], bh[p][s], bh[p][s + 1]);
                }
            }
        }
        __syncthreads();
    }

    #pragma unroll
    for (int mi = 0; mi < 4; mi++) {
        int r0 = m0 + wm + mi * 16 + (l >> 2);
        #pragma unroll
        for (int nj = 0; nj < 4; nj++) {
            int col = n0 + wn + nj * 8 + (l & 3) * 2;
            float b0 = bias[col], b1 = bias[col + 1];
            #pragma unroll
            for (int half = 0; half < 2; half++) {
                int r = r0 + half * 8;
                float v0 = (c[mi][nj][half * 2 + 0] + b0) * scale;
                float v1 = (c[mi][nj][half * 2 + 1] + b1) * scale;
                *(__half2*)(out + (size_t)r * HID + col) =
                    __halves2half2(__float2half(v0), __float2half(v1));
            }
        }
    }
}

// ================= fp16 single-term GEMM (Wo) =================
__global__ __launch_bounds__(256) void gemm_fp16(
    const __half* __restrict__ A, int lda, const __half* __restrict__ B,
    int Kdim, const float* __restrict__ bias,
    __half* __restrict__ Ch, int ldch)
{
    extern __shared__ __half smh[];
    const int tid = threadIdx.x;
    const int w = tid >> 5, l = tid & 31;
    const int m0 = blockIdx.y * 128;
    const int n0 = blockIdx.x * 128;
    const int wm = (w >> 2) * 64;
    const int wn = (w & 3) * 32;

    float c[4][4][4];
    #pragma unroll
    for (int i = 0; i < 4; i++)
        #pragma unroll
        for (int j = 0; j < 4; j++)
            #pragma unroll
            for (int q = 0; q < 4; q++) c[i][j][q] = 0.f;

    const uint32_t sbase = smem_u32(smh);
    const int aRow = wm + (l & 15), aKof = (l >> 4) * 8;
    const int bRow = wn + (l >> 4) * 8 + (l & 7), bKof = ((l >> 3) & 1) * 8;
    const int nChunks = Kdim >> 6;

    auto issue = [&](int ch) {
        const uint32_t dstBase = sbase + (uint32_t)((ch & 1) * FSTAGE * 2);
        const int k0 = ch << 6;
        #pragma unroll
        for (int i = 0; i < 4; i++) {
            int t = tid + i * 256;
            int row = t >> 3, c8 = (t & 7) * 8;
            uint32_t d = dstBase + (uint32_t)((row * GSTRIDE + c8) * 2);
            cp16(d,            A + (size_t)(m0 + row) * lda  + k0 + c8);
            cp16(d + GBUF * 2, B + (size_t)(n0 + row) * Kdim + k0 + c8);
        }
    };

    issue(0); CP_COMMIT();
    for (int ch = 0; ch < nChunks; ch++) {
        CP_WAIT0();
        __syncthreads();
        if (ch + 1 < nChunks) { issue(ch + 1); CP_COMMIT(); }

        const uint32_t sb = sbase + (uint32_t)((ch & 1) * FSTAGE * 2);
        const uint32_t aB = sb + (uint32_t)((aRow * GSTRIDE + aKof) * 2);
        const uint32_t bB = sb + GBUF * 2 + (uint32_t)((bRow * GSTRIDE + bKof) * 2);

        #pragma unroll
        for (int ks = 0; ks < 4; ks++) {
            const uint32_t kb = (uint32_t)(ks * 16 * 2);
            uint32_t ah[4][4], bh[2][4];
            #pragma unroll
            for (int mi = 0; mi < 4; mi++)
                ldsm_x4(ah[mi], aB + (uint32_t)(mi * 16 * GSTRIDE * 2) + kb);
            #pragma unroll
            for (int p = 0; p < 2; p++)
                ldsm_x4(bh[p], bB + (uint32_t)(p * 16 * GSTRIDE * 2) + kb);
            #pragma unroll
            for (int mi = 0; mi < 4; mi++) {
                #pragma unroll
                for (int nj = 0; nj < 4; nj++) {
                    const int p = nj >> 1, s = (nj & 1) * 2;
                    mma16816h(c[mi][nj], ah[mi], bh[p][s], bh[p][s + 1]);
                }
            }
        }
        __syncthreads();
    }

    #pragma unroll
    for (int mi = 0; mi < 4; mi++) {
        int r0 = m0 + wm + mi * 16 + (l >> 2);
        #pragma unroll
        for (int nj = 0; nj < 4; nj++) {
            int col = n0 + wn + nj * 8 + (l & 3) * 2;
            float b0 = bias[col], b1 = bias[col + 1];
            #pragma unroll
            for (int half = 0; half < 2; half++) {
                int r = r0 + half * 8;
                float v0 = c[mi][nj][half * 2 + 0] + b0;
                float v1 = c[mi][nj][half * 2 + 1] + b1;
                *(__half2*)(Ch + (size_t)r * ldch + col) =
                    __halves2half2(__float2half(v0), __float2half(v1));
            }
        }
    }
}

// ================= fused FFN: out = sigmoid(cat@W1+b1) * (cat@W2+b2) =================
#define E3STG (3 * GBUF)

__global__ __launch_bounds__(256) void gemm_ffn(
    const __half* __restrict__ A, const __half* __restrict__ B1,
    const __half* __restrict__ B2,
    const float* __restrict__ b1p, const float* __restrict__ b2p,
    float* __restrict__ Cf)
{
    extern __shared__ __half smh[];
    const int tid = threadIdx.x;
    const int w = tid >> 5, l = tid & 31;
    const int m0 = blockIdx.y * 128;
    const int n0 = blockIdx.x * 128;
    const int wm = (w >> 2) * 64;
    const int wn = (w & 3) * 32;
    const int Kdim = 2 * HID;

    float c1[4][4][4], c2[4][4][4];
    #pragma unroll
    for (int i = 0; i < 4; i++)
        #pragma unroll
        for (int j = 0; j < 4; j++)
            #pragma unroll
            for (int q = 0; q < 4; q++) { c1[i][j][q] = 0.f; c2[i][j][q] = 0.f; }

    const uint32_t sbase = smem_u32(smh);
    const int aRow = wm + (l & 15), aKof = (l >> 4) * 8;
    const int bRow = wn + (l >> 4) * 8 + (l & 7), bKof = ((l >> 3) & 1) * 8;
    const int nChunks = Kdim >> 6;   // 24

    auto issue = [&](int ch) {
        const uint32_t dstBase = sbase + (uint32_t)((ch & 1) * E3STG * 2);
        const int k0 = ch << 6;
        #pragma unroll
        for (int i = 0; i < 4; i++) {
            int t = tid + i * 256;
            int row = t >> 3, c8 = (t & 7) * 8;
            uint32_t d = dstBase + (uint32_t)((row * GSTRIDE + c8) * 2);
            cp16(d,                A  + (size_t)(m0 + row) * Kdim + k0 + c8);
            cp16(d + GBUF * 2,     B1 + (size_t)(n0 + row) * Kdim + k0 + c8);
            cp16(d + 2 * GBUF * 2, B2 + (size_t)(n0 + row) * Kdim + k0 + c8);
        }
    };

    issue(0); CP_COMMIT();
    for (int ch = 0; ch < nChunks; ch++) {
        CP_WAIT0();
        __syncthreads();
        if (ch + 1 < nChunks) { issue(ch + 1); CP_COMMIT(); }

        const uint32_t sb = sbase + (uint32_t)((ch & 1) * E3STG * 2);
        const uint32_t aB  = sb + (uint32_t)((aRow * GSTRIDE + aKof) * 2);
        const uint32_t b1B = sb + GBUF * 2 + (uint32_t)((bRow * GSTRIDE + bKof) * 2);
        const uint32_t b2B = b1B + GBUF * 2;

        #pragma unroll
        for (int ks = 0; ks < 4; ks++) {
            const uint32_t kb = (uint32_t)(ks * 16 * 2);
            uint32_t ah[4][4], bh1[2][4], bh2[2][4];
            #pragma unroll
            for (int mi = 0; mi < 4; mi++)
                ldsm_x4(ah[mi], aB + (uint32_t)(mi * 16 * GSTRIDE * 2) + kb);
            #pragma unroll
            for (int p = 0; p < 2; p++) {
                ldsm_x4(bh1[p], b1B + (uint32_t)(p * 16 * GSTRIDE * 2) + kb);
                ldsm_x4(bh2[p], b2B + (uint32_t)(p * 16 * GSTRIDE * 2) + kb);
            }
            #pragma unroll
            for (int mi = 0; mi < 4; mi++) {
                #pragma unroll
                for (int nj = 0; nj < 4; nj++) {
                    const int p = nj >> 1, s = (nj & 1) * 2;
                    mma16816h(c1[mi][nj], ah[mi], bh1[p][s], bh1[p][s + 1]);
                    mma16816h(c2[mi][nj], ah[mi], bh2[p][s], bh2[p][s + 1]);
                }
            }
        }
        __syncthreads();
    }

    #pragma unroll
    for (int mi = 0; mi < 4; mi++) {
        int r0 = m0 + wm + mi * 16 + (l >> 2);
        #pragma unroll
        for (int nj = 0; nj < 4; nj++) {
            int col = n0 + wn + nj * 8 + (l & 3) * 2;
            float bb1a = b1p[col], bb1b = b1p[col + 1];
            float bb2a = b2p[col], bb2b = b2p[col + 1];
            #pragma unroll
            for (int half = 0; half < 2; half++) {
                int r = r0 + half * 8;
                float g0 = c1[mi][nj][half * 2 + 0] + bb1a;
                float g1 = c1[mi][nj][half * 2 + 1] + bb1b;
                float v0 = c2[mi][nj][half * 2 + 0] + bb2a;
                float v1 = c2[mi][nj][half * 2 + 1] + bb2b;
                v0 *= 1.f / (1.f + __expf(-g0));
                v1 *= 1.f / (1.f + __expf(-g1));
                *(float2*)(Cf + (size_t)r * HID + col) = make_float2(v0, v1);
            }
        }
    }
}

// ================= attention v7: two-pass, no sE, probs streamed from registers =================
// smem bytes:
//   sQ  [0, 9216)                 : 64 x 72 fp16
//   stages 2 x 36864 [9216, 82944): pass1: 256 keys K ; pass2: 128 keys K + 128 keys V
//   sMask [82944, 87040)          : 1024 int
//   sSum  [87040, 87296)          : 64 float
//   sInv  [87296, 87552)          : 64 float
//   sPart overlays stage region after main loops (3 x 4096 floats)
#define KVST 72
#define CSTG 18432
#define ASTG 36864
#define ATTN_SMEM 87552

__global__ __launch_bounds__(512) void attn_mma(
    const __half* __restrict__ qf, const __half* __restrict__ kpf,
    const __half* __restrict__ vpf,
    const int* __restrict__ mask, float* __restrict__ attn_out,
    __half* __restrict__ xf)
{
    extern __shared__ char sab[];
    __half* sQ = (__half*)(sab);
    int*   sMask = (int*)(sab + 82944);
    float* sSum  = (float*)(sab + 87040);
    float* sInv  = (float*)(sab + 87296);
    float* sPart = (float*)(sab + 9216);

    const int tid = threadIdx.x, w = tid >> 5, l = tid & 31;
    const int q0 = blockIdx.x * 64, h = blockIdx.y, b = blockIdx.z;

    const uint32_t uQ  = smem_u32(sab);
    const uint32_t uK0 = uQ + 9216;

    // load Q tile (64 x 64 fp16) + mask + zero sums
    {
        int r = tid >> 3, c8 = (tid & 7) * 8;
        size_t g = ((size_t)(b * SS + q0 + r)) * HID + h * HD + c8;
        *(uint4*)(sQ + r * KVST + c8) = *(const uint4*)(qf + g);
    }
    for (int k = tid; k < SS; k += 512) sMask[k] = mask[b * SS + k];
    if (tid < 64) sSum[tid] = 0.f;

    const int mg = w & 3;           // 16-query row group
    const int sub = w >> 2;         // key sub-slice index
    const int bRowL = (l >> 4) * 8 + (l & 7);
    const int bKofL = ((l >> 3) & 1) * 8;
    const uint32_t aLaneOff = (uint32_t)(((mg * 16 + (l & 15)) * KVST + (l >> 4) * 8) * 2);

    // pass-1 issue: 256-key K chunk fills whole stage
    auto issueK = [&](int chunk, int st) {
        const uint32_t dst = uK0 + (uint32_t)(st * ASTG);
        const int r0 = chunk * 256;
        #pragma unroll
        for (int i = 0; i < 4; i++) {
            int t = tid + i * 512;
            int row = t >> 3, c8 = (t & 7) * 8;
            size_t g = ((size_t)(b * SS + r0 + row)) * HID + h * HD + c8;
            cp16(dst + (uint32_t)((row * KVST + c8) * 2), kpf + g);
        }
    };
    // pass-2 issue: 128-key K + V chunk
    auto issueKV = [&](int chunk, int st) {
        const uint32_t dst = uK0 + (uint32_t)(st * ASTG);
        const int r0 = chunk * 128;
        #pragma unroll
        for (int i = 0; i < 2; i++) {
            int t = tid + i * 512;
            int row = t >> 3, c8 = (t & 7) * 8;
            uint32_t d = dst + (uint32_t)((row * KVST + c8) * 2);
            size_t g = ((size_t)(b * SS + r0 + row)) * HID + h * HD + c8;
            cp16(d,        kpf + g);
            cp16(d + CSTG, vpf + g);
        }
    };

    // ---------- Pass 1: row sums of e = mask*exp(QK^T) ; 4 chunks x 256 keys ----------
    float sum_lo = 0.f, sum_hi = 0.f;
    issueK(0, 0); CP_COMMIT();
    for (int ch = 0; ch < 4; ch++) {
        CP_WAIT0();
        __syncthreads();
        if (ch < 3) issueK(ch + 1, (ch + 1) & 1);
        else        issueKV(0, 0);       // prefetch pass-2 chunk 0
        CP_COMMIT();

        const uint32_t sbK = uK0 + (uint32_t)((ch & 1) * ASTG);
        const int kw0 = ch * 256 + sub * 64;

        float ea[4][2][4];
        #pragma unroll
        for (int p = 0; p < 4; p++)
            #pragma unroll
            for (int t = 0; t < 2; t++)
                #pragma unroll
                for (int q = 0; q < 4; q++) ea[p][t][q] = 0.f;

        #pragma unroll
        for (int ks = 0; ks < 4; ks++) {
            uint32_t ah[4], bk[4][4];
            ldsm_x4(ah, uQ + aLaneOff + (uint32_t)(ks * 16 * 2));
            #pragma unroll
            for (int p = 0; p < 4; p++)
                ldsm_x4(bk[p], sbK + (uint32_t)(((sub * 64 + p * 16 + bRowL) * KVST + ks * 16 + bKofL) * 2));
            #pragma unroll
            for (int p = 0; p < 4; p++) {
                #pragma unroll
                for (int t = 0; t < 2; t++)
                    mma16816h(ea[p][t], ah, bk[p][t * 2], bk[p][t * 2 + 1]);
            }
        }
        #pragma unroll
        for (int p = 0; p < 4; p++) {
            #pragma unroll
            for (int t = 0; t < 2; t++) {
                int kcol = kw0 + p * 16 + t * 8 + (l & 3) * 2;
                int mk0 = sMask[kcol], mk1 = sMask[kcol + 1];
                float e00 = mk0 ? __expf(fminf(ea[p][t][0], 11.f)) : 0.f;
                float e01 = mk1 ? __expf(fminf(ea[p][t][1], 11.f)) : 0.f;
                float e10 = mk0 ? __expf(fminf(ea[p][t][2], 11.f)) : 0.f;
                float e11 = mk1 ? __expf(fminf(ea[p][t][3], 11.f)) : 0.f;
                sum_lo += e00 + e01;
                sum_hi += e10 + e11;
            }
        }
    }
    // reduce sums: within quad (lanes sharing l>>2), then cross-warp via smem atomics
    #pragma unroll
    for (int o = 1; o < 4; o <<= 1) {
        sum_lo += __shfl_xor_sync(0xffffffffu, sum_lo, o);
        sum_hi += __shfl_xor_sync(0xffffffffu, sum_hi, o);
    }
    if ((l & 3) == 0) {
        atomicAdd(&sSum[mg * 16 + (l >> 2)], sum_lo);
        atomicAdd(&sSum[mg * 16 + (l >> 2) + 8], sum_hi);
    }
    __syncthreads();
    if (tid < 64) sInv[tid] = 1.f / sSum[tid];

    // ---------- Pass 2: recompute QK, p = e*inv -> gmem probs + inline PV ----------
    float xa[8][4];
    #pragma unroll
    for (int j = 0; j < 8; j++)
        #pragma unroll
        for (int q = 0; q < 4; q++) xa[j][q] = 0.f;

    float* obase = attn_out + ((size_t)((b * NH + h) * SS + q0)) * SS;

    for (int ch = 0; ch < 8; ch++) {
        CP_WAIT0();
        __syncthreads();      // also publishes sInv on first iteration
        if (ch < 7) { issueKV(ch + 1, (ch + 1) & 1); CP_COMMIT(); }

        const uint32_t sbK = uK0 + (uint32_t)((ch & 1) * ASTG);
        const uint32_t sbV = sbK + CSTG;
        const int kw0 = ch * 128 + sub * 32;

        float ea[2][2][4];
        #pragma unroll
        for (int p = 0; p < 2; p++)
            #pragma unroll
            for (int t = 0; t < 2; t++)
                #pragma unroll
                for (int q = 0; q < 4; q++) ea[p][t][q] = 0.f;

        #pragma unroll
        for (int ks = 0; ks < 4; ks++) {
            uint32_t ah[4], bk[2][4];
            ldsm_x4(ah, uQ + aLaneOff + (uint32_t)(ks * 16 * 2));
            #pragma unroll
            for (int p = 0; p < 2; p++)
                ldsm_x4(bk[p], sbK + (uint32_t)(((sub * 32 + p * 16 + bRowL) * KVST + ks * 16 + bKofL) * 2));
            #pragma unroll
            for (int p = 0; p < 2; p++) {
                #pragma unroll
                for (int t = 0; t < 2; t++)
                    mma16816h(ea[p][t], ah, bk[p][t * 2], bk[p][t * 2 + 1]);
            }
        }

        const int rlo = mg * 16 + (l >> 2);
        const float inv_lo = sInv[rlo];
        const float inv_hi = sInv[rlo + 8];

        uint32_t aF[2][4];
        #pragma unroll
        for (int p = 0; p < 2; p++) {
            #pragma unroll
            for (int t = 0; t < 2; t++) {
                int kcol = kw0 + p * 16 + t * 8 + (l & 3) * 2;
                int mk0 = sMask[kcol], mk1 = sMask[kcol + 1];
                float p00 = (mk0 ? __expf(fminf(ea[p][t][0], 11.f)) : 0.f) * inv_lo;
                float p01 = (mk1 ? __expf(fminf(ea[p][t][1], 11.f)) : 0.f) * inv_lo;
                float p10 = (mk0 ? __expf(fminf(ea[p][t][2], 11.f)) : 0.f) * inv_hi;
                float p11 = (mk1 ? __expf(fminf(ea[p][t][3], 11.f)) : 0.f) * inv_hi;
                *(float2*)(obase + (size_t)rlo * SS + kcol)       = make_float2(p00, p01);
                *(float2*)(obase + (size_t)(rlo + 8) * SS + kcol) = make_float2(p10, p11);
                __half2 hlo = __halves2half2(__float2half(p00), __float2half(p01));
                __half2 hhi = __halves2half2(__float2half(p10), __float2half(p11));
                aF[p][t * 2 + 0] = *(uint32_t*)&hlo;
                aF[p][t * 2 + 1] = *(uint32_t*)&hhi;
            }
        }

        // inline PV: xa += p_chunk @ V_chunk (16q x 32k x 64d)
        #pragma unroll
        for (int p = 0; p < 2; p++) {
            #pragma unroll
            for (int dt = 0; dt < 4; dt++) {
                uint32_t bv[4];
                ldsm_x4_t(bv, sbV + (uint32_t)(((sub * 32 + p * 16 + (l & 15)) * KVST + dt * 16 + (l >> 4) * 8) * 2));
                mma16816h(xa[dt * 2 + 0], aF[p], bv[0], bv[1]);
                mma16816h(xa[dt * 2 + 1], aF[p], bv[2], bv[3]);
            }
        }
    }
    __syncthreads();

    // ---------- x reduction over 4 key-slices (sub) via smem overlay ----------
    if (sub > 0) {
        float* dst = sPart + (sub - 1) * 4096;
        #pragma unroll
        for (int j = 0; j < 8; j++)
            #pragma unroll
            for (int v = 0; v < 4; v++) {
                int row = mg * 16 + (l >> 2) + (v >> 1) * 8;
                int col = (j >> 1) * 16 + (j & 1) * 8 + (l & 3) * 2 + (v & 1);
                dst[row * 64 + col] = xa[j][v];
            }
    }
    __syncthreads();
    if (sub == 0) {
        #pragma unroll
        for (int j = 0; j < 8; j++) {
            #pragma unroll
            for (int hf = 0; hf < 2; hf++) {
                int row = mg * 16 + (l >> 2) + hf * 8;
                int col = (j >> 1) * 16 + (j & 1) * 8 + (l & 3) * 2;
                float x0 = xa[j][hf * 2 + 0];
                float x1 = xa[j][hf * 2 + 1];
                #pragma unroll
                for (int p = 0; p < 3; p++) {
                    x0 += sPart[p * 4096 + row * 64 + col];
                    x1 += sPart[p * 4096 + row * 64 + col + 1];
                }
                size_t g = ((size_t)(b * SS + q0 + row)) * HID + h * HD + col;
                *(__half2*)(xf + g) = __halves2half2(__float2half(x0), __float2half(x1));
            }
        }
    }
}

// ================= launch =================
extern "C" void kernel_launch(void* const* d_in, const int* in_sizes, int n_in,
                              void* d_out, int out_size)
{
    const float* query = (const float*)d_in[0];
    const float* key_t = (const float*)d_in[1];
    const float* value = (const float*)d_in[2];
    const int*   mask  = (const int*)d_in[3];
    const float* Wq = (const float*)d_in[4];  const float* bq = (const float*)d_in[5];
    const float* Wk = (const float*)d_in[6];  const float* bk = (const float*)d_in[7];
    const float* Wv = (const float*)d_in[8];  const float* bv = (const float*)d_in[9];
    const float* Wo = (const float*)d_in[10]; const float* bo = (const float*)d_in[11];
    const float* W1 = (const float*)d_in[12]; const float* b1 = (const float*)d_in[13];
    const float* W2 = (const float*)d_in[14]; const float* b2 = (const float*)d_in[15];

    float* out       = (float*)d_out;
    float* out_gated = out;
    float* out_attn  = out + MH;

    __half *kf, *vf, *qfp, *kpf, *vpf, *xf, *cat, *wqk, *wfo, *wf;
    cudaGetSymbolAddress((void**)&kf, g_kf);
    cudaGetSymbolAddress((void**)&vf, g_vf);
    cudaGetSymbolAddress((void**)&qfp, g_qf);
    cudaGetSymbolAddress((void**)&kpf, g_kpf);
    cudaGetSymbolAddress((void**)&vpf, g_vpf);
    cudaGetSymbolAddress((void**)&xf, g_xf);
    cudaGetSymbolAddress((void**)&cat, g_cat);
    cudaGetSymbolAddress((void**)&wqk, g_wqk);
    cudaGetSymbolAddress((void**)&wfo, g_wfo);
    cudaGetSymbolAddress((void**)&wf, g_wf);

    size_t fsmem = (size_t)2 * FSTAGE * 2;   // 73728 B
    size_t esmem = (size_t)2 * E3STG * 2;    // 110592 B
    cudaFuncSetAttribute(gemm_qkv, cudaFuncAttributeMaxDynamicSharedMemorySize, (int)fsmem);
    cudaFuncSetAttribute(gemm_fp16, cudaFuncAttributeMaxDynamicSharedMemorySize, (int)fsmem);
    cudaFuncSetAttribute(gemm_ffn, cudaFuncAttributeMaxDynamicSharedMemorySize, (int)esmem);
    cudaFuncSetAttribute(attn_mma, cudaFuncAttributeMaxDynamicSharedMemorySize, ATTN_SMEM);

    const int actBlocks = (MROWS * HID / 4 + 255) / 256;
    dim3 wblk(32, 8);
    dim3 ggrid(HID / 128, MROWS / 128);      // (6, 64)

    // --- input conversions + weight splits ---
    conv3<<<dim3(actBlocks, 3), 256>>>(query, key_t, value, cat, kf, vf);
    split_wqk3<<<dim3(HID / 32, HID / 32, 3), wblk>>>(Wq, Wk, Wv, wqk);

    // --- QKV projections (fp16 single-term; Q pre-scaled 1/8) ---
    gemm_qkv<<<dim3(HID / 128, MROWS / 128, 3), 256, fsmem>>>(
        cat + HID, kf, vf, wqk, bq, bk, bv, qfp, kpf, vpf);

    // --- attention (two-pass, no sE) ---
    attn_mma<<<dim3(SS / 64, NH, BB), 512, ATTN_SMEM>>>(
        qfp, kpf, vpf, mask, out_attn, xf);

    // --- Wo (fp16) -> cat[:, 0:768] ---
    split_w_fp16<<<dim3(HID / 32, HID / 32), wblk>>>(Wo, HID, HID, wfo);
    gemm_fp16<<<ggrid, 256, fsmem>>>(
        xf, HID, wfo, HID, bo, cat, 2 * HID);

    // --- fused FFN (fp16, K=1536): out = sigmoid(cat@W1+b1) * (cat@W2+b2) ---
    split_wf2<<<dim3(HID / 32, 2 * HID / 32, 2), wblk>>>(W1, W2, wf);
    gemm_ffn<<<ggrid, 256, esmem>>>(
        cat, wf, wf + (size_t)2 * HID * HID, b1, b2, out_gated);
}

// round 15
// speedup vs baseline: 1.1035x; 1.1035x over previous
#include <cuda_runtime.h>
#include <cuda_fp16.h>
#include <math.h>
#include <stdint.h>

#define BB 8
#define SS 1024
#define HID 768
#define NH 12
#define HD 64
#define MROWS (BB*SS)   // 8192
#define MH ((size_t)MROWS*HID)

// ---------------- scratch (device globals; no allocation allowed) ----------------
__device__ __align__(256) __half g_kf [MH];                     // raw key fp16
__device__ __align__(256) __half g_vf [MH];                     // raw value fp16
__device__ __align__(256) __half g_qf [MH];                     // projected Q (fp16, prescaled)
__device__ __align__(256) __half g_kpf[MH];                     // projected K (fp16)
__device__ __align__(256) __half g_vpf[MH];                     // projected V (fp16)

__device__ __align__(256) __half g_xf [MH];
__device__ __align__(256) __half g_cat[2*MH];
__device__ __align__(256) __half g_wqk[(size_t)3*HID*HID];      // Wq,Wk,Wv fp16 [N][K]
__device__ __align__(256) __half g_wfo[(size_t)HID*HID];
__device__ __align__(256) __half g_wf [(size_t)2*2*HID*HID];    // W1,W2 fp16 [N][K]

// ================= helpers =================
__device__ __forceinline__ uint32_t smem_u32(const void* p) {
    uint32_t a;
    asm("{ .reg .u64 t; cvta.to.shared.u64 t, %1; cvt.u32.u64 %0, t; }" : "=r"(a) : "l"(p));
    return a;
}
__device__ __forceinline__ void ldsm_x4(uint32_t* r, uint32_t addr) {
    asm volatile("ldmatrix.sync.aligned.m8n8.x4.shared.b16 {%0,%1,%2,%3}, [%4];"
                 : "=r"(r[0]), "=r"(r[1]), "=r"(r[2]), "=r"(r[3]) : "r"(addr));
}
__device__ __forceinline__ void ldsm_x4_t(uint32_t* r, uint32_t addr) {
    asm volatile("ldmatrix.sync.aligned.m8n8.x4.trans.shared.b16 {%0,%1,%2,%3}, [%4];"
                 : "=r"(r[0]), "=r"(r[1]), "=r"(r[2]), "=r"(r[3]) : "r"(addr));
}
__device__ __forceinline__ void mma16816h(float* c, const uint32_t* a, uint32_t b0, uint32_t b1) {
    asm volatile("mma.sync.aligned.m16n8k16.row.col.f32.f16.f16.f32 "
                 "{%0,%1,%2,%3}, {%4,%5,%6,%7}, {%8,%9}, {%0,%1,%2,%3};"
                 : "+f"(c[0]), "+f"(c[1]), "+f"(c[2]), "+f"(c[3])
                 : "r"(a[0]), "r"(a[1]), "r"(a[2]), "r"(a[3]), "r"(b0), "r"(b1));
}
__device__ __forceinline__ void cp16(uint32_t dst, const void* src) {
    asm volatile("cp.async.cg.shared.global [%0], [%1], 16;" :: "r"(dst), "l"(src));
}
#define CP_COMMIT() asm volatile("cp.async.commit_group;" ::: "memory")
#define CP_WAIT0()  asm volatile("cp.async.wait_group 0;" ::: "memory")

// ================= convert / weight-split kernels =================
__global__ void conv3(const float* __restrict__ q, const float* __restrict__ k,
                      const float* __restrict__ v,
                      __half* __restrict__ cat, __half* __restrict__ kf,
                      __half* __restrict__ vf)
{
    const int z = blockIdx.y;
    const float* src = (z == 0) ? q : (z == 1) ? k : v;
    size_t total = MH / 4;
    for (size_t i = (size_t)blockIdx.x * blockDim.x + threadIdx.x; i < total;
         i += (size_t)gridDim.x * blockDim.x) {
        size_t e = i * 4;
        int m = (int)(e / HID), c = (int)(e % HID);
        float4 x = *(const float4*)(src + e);
        __half* dst = (z == 0) ? (cat + (size_t)m * (2 * HID) + HID + c)
                    : (z == 1) ? (kf + e) : (vf + e);
        *(__half2*)(dst)     = __halves2half2(__float2half(x.x), __float2half(x.y));
        *(__half2*)(dst + 2) = __halves2half2(__float2half(x.z), __float2half(x.w));
    }
}

__global__ void split_wqk3(const float* __restrict__ Wa, const float* __restrict__ Wb,
                           const float* __restrict__ Wc, __half* __restrict__ out)
{
    __shared__ float t[32][33];
    const int z = blockIdx.z;
    const float* W = (z == 0) ? Wa : (z == 1) ? Wb : Wc;
    __half* O = out + (size_t)z * HID * HID;
    int n0 = blockIdx.x * 32, k0 = blockIdx.y * 32;
    int tx = threadIdx.x, ty = threadIdx.y;
    for (int j = ty; j < 32; j += 8)
        t[j][tx] = W[(size_t)(k0 + j) * HID + n0 + tx];
    __syncthreads();
    for (int j = ty; j < 32; j += 8)
        O[(size_t)(n0 + j) * HID + k0 + tx] = __float2half(t[tx][j]);
}

__global__ void split_w_fp16(const float* __restrict__ W, int K, int N,
                             __half* __restrict__ out)
{
    __shared__ float t[32][33];
    int n0 = blockIdx.x * 32, k0 = blockIdx.y * 32;
    int tx = threadIdx.x, ty = threadIdx.y;
    for (int j = ty; j < 32; j += 8)
        t[j][tx] = W[(size_t)(k0 + j) * N + n0 + tx];
    __syncthreads();
    for (int j = ty; j < 32; j += 8)
        out[(size_t)(n0 + j) * K + k0 + tx] = __float2half(t[tx][j]);
}

__global__ void split_wf2(const float* __restrict__ Wa, const float* __restrict__ Wb,
                          __half* __restrict__ out)
{
    __shared__ float t[32][33];
    const int z = blockIdx.z;
    const float* W = (z == 0) ? Wa : Wb;
    __half* O = out + (size_t)z * 2 * HID * HID;
    int n0 = blockIdx.x * 32, k0 = blockIdx.y * 32;
    int tx = threadIdx.x, ty = threadIdx.y;
    for (int j = ty; j < 32; j += 8)
        t[j][tx] = W[(size_t)(k0 + j) * HID + n0 + tx];
    __syncthreads();
    for (int j = ty; j < 32; j += 8)
        O[(size_t)(n0 + j) * (2 * HID) + k0 + tx] = __float2half(t[tx][j]);
}

// ================= fp16 QKV projection GEMM (batched z = 0,1,2) =================
#define GSTRIDE 72
#define GBUF (128 * GSTRIDE)
#define FSTAGE (2 * GBUF)

__global__ __launch_bounds__(256) void gemm_qkv(
    const __half* __restrict__ Aq, const __half* __restrict__ Ak,
    const __half* __restrict__ Av, const __half* __restrict__ Bw,
    const float* __restrict__ bq, const float* __restrict__ bk,
    const float* __restrict__ bv,
    __half* __restrict__ oq, __half* __restrict__ ok, __half* __restrict__ ov)
{
    extern __shared__ __half smh[];
    const int tid = threadIdx.x;
    const int w = tid >> 5, l = tid & 31;
    const int z = blockIdx.z;
    const int m0 = blockIdx.y * 128;
    const int n0 = blockIdx.x * 128;
    const int wm = (w >> 2) * 64;
    const int wn = (w & 3) * 32;

    const __half* A = (z == 0) ? Aq : (z == 1) ? Ak : Av;
    const int lda = (z == 0) ? 2 * HID : HID;
    const __half* B = Bw + (size_t)z * HID * HID;
    const float* bias = (z == 0) ? bq : (z == 1) ? bk : bv;
    const float scale = (z == 0) ? 0.125f : 1.f;
    __half* out = (z == 0) ? oq : (z == 1) ? ok : ov;

    float c[4][4][4];
    #pragma unroll
    for (int i = 0; i < 4; i++)
        #pragma unroll
        for (int j = 0; j < 4; j++)
            #pragma unroll
            for (int q = 0; q < 4; q++) c[i][j][q] = 0.f;

    const uint32_t sbase = smem_u32(smh);
    const int aRow = wm + (l & 15), aKof = (l >> 4) * 8;
    const int bRow = wn + (l >> 4) * 8 + (l & 7), bKof = ((l >> 3) & 1) * 8;
    const int nChunks = HID >> 6;

    auto issue = [&](int ch) {
        const uint32_t dstBase = sbase + (uint32_t)((ch & 1) * FSTAGE * 2);
        const int k0 = ch << 6;
        #pragma unroll
        for (int i = 0; i < 4; i++) {
            int t = tid + i * 256;
            int row = t >> 3, c8 = (t & 7) * 8;
            uint32_t d = dstBase + (uint32_t)((row * GSTRIDE + c8) * 2);
            cp16(d,            A + (size_t)(m0 + row) * lda + k0 + c8);
            cp16(d + GBUF * 2, B + (size_t)(n0 + row) * HID + k0 + c8);
        }
    };

    issue(0); CP_COMMIT();
    for (int ch = 0; ch < nChunks; ch++) {
        CP_WAIT0();
        __syncthreads();
        if (ch + 1 < nChunks) { issue(ch + 1); CP_COMMIT(); }

        const uint32_t sb = sbase + (uint32_t)((ch & 1) * FSTAGE * 2);
        const uint32_t aB = sb + (uint32_t)((aRow * GSTRIDE + aKof) * 2);
        const uint32_t bB = sb + GBUF * 2 + (uint32_t)((bRow * GSTRIDE + bKof) * 2);

        #pragma unroll
        for (int ks = 0; ks < 4; ks++) {
            const uint32_t kb = (uint32_t)(ks * 16 * 2);
            uint32_t ah[4][4], bh[2][4];
            #pragma unroll
            for (int mi = 0; mi < 4; mi++)
                ldsm_x4(ah[mi], aB + (uint32_t)(mi * 16 * GSTRIDE * 2) + kb);
            #pragma unroll
            for (int p = 0; p < 2; p++)
                ldsm_x4(bh[p], bB + (uint32_t)(p * 16 * GSTRIDE * 2) + kb);
            #pragma unroll
            for (int mi = 0; mi < 4; mi++) {
                #pragma unroll
                for (int nj = 0; nj < 4; nj++) {
                    const int p = nj >> 1, s = (nj & 1) * 2;
                    mma16816h(c[mi][nj], ah[mi], bh[p][s], bh[p][s + 1]);
                }
            }
        }
        __syncthreads();
    }

    #pragma unroll
    for (int mi = 0; mi < 4; mi++) {
        int r0 = m0 + wm + mi * 16 + (l >> 2);
        #pragma unroll
        for (int nj = 0; nj < 4; nj++) {
            int col = n0 + wn + nj * 8 + (l & 3) * 2;
            float b0 = bias[col], b1 = bias[col + 1];
            #pragma unroll
            for (int half = 0; half < 2; half++) {
                int r = r0 + half * 8;
                float v0 = (c[mi][nj][half * 2 + 0] + b0) * scale;
                float v1 = (c[mi][nj][half * 2 + 1] + b1) * scale;
                *(__half2*)(out + (size_t)r * HID + col) =
                    __halves2half2(__float2half(v0), __float2half(v1));
            }
        }
    }
}

// ================= fp16 single-term GEMM (Wo) =================
__global__ __launch_bounds__(256) void gemm_fp16(
    const __half* __restrict__ A, int lda, const __half* __restrict__ B,
    int Kdim, const float* __restrict__ bias,
    __half* __restrict__ Ch, int ldch)
{
    extern __shared__ __half smh[];
    const int tid = threadIdx.x;
    const int w = tid >> 5, l = tid & 31;
    const int m0 = blockIdx.y * 128;
    const int n0 = blockIdx.x * 128;
    const int wm = (w >> 2) * 64;
    const int wn = (w & 3) * 32;

    float c[4][4][4];
    #pragma unroll
    for (int i = 0; i < 4; i++)
        #pragma unroll
        for (int j = 0; j < 4; j++)
            #pragma unroll
            for (int q = 0; q < 4; q++) c[i][j][q] = 0.f;

    const uint32_t sbase = smem_u32(smh);
    const int aRow = wm + (l & 15), aKof = (l >> 4) * 8;
    const int bRow = wn + (l >> 4) * 8 + (l & 7), bKof = ((l >> 3) & 1) * 8;
    const int nChunks = Kdim >> 6;

    auto issue = [&](int ch) {
        const uint32_t dstBase = sbase + (uint32_t)((ch & 1) * FSTAGE * 2);
        const int k0 = ch << 6;
        #pragma unroll
        for (int i = 0; i < 4; i++) {
            int t = tid + i * 256;
            int row = t >> 3, c8 = (t & 7) * 8;
            uint32_t d = dstBase + (uint32_t)((row * GSTRIDE + c8) * 2);
            cp16(d,            A + (size_t)(m0 + row) * lda  + k0 + c8);
            cp16(d + GBUF * 2, B + (size_t)(n0 + row) * Kdim + k0 + c8);
        }
    };

    issue(0); CP_COMMIT();
    for (int ch = 0; ch < nChunks; ch++) {
        CP_WAIT0();
        __syncthreads();
        if (ch + 1 < nChunks) { issue(ch + 1); CP_COMMIT(); }

        const uint32_t sb = sbase + (uint32_t)((ch & 1) * FSTAGE * 2);
        const uint32_t aB = sb + (uint32_t)((aRow * GSTRIDE + aKof) * 2);
        const uint32_t bB = sb + GBUF * 2 + (uint32_t)((bRow * GSTRIDE + bKof) * 2);

        #pragma unroll
        for (int ks = 0; ks < 4; ks++) {
            const uint32_t kb = (uint32_t)(ks * 16 * 2);
            uint32_t ah[4][4], bh[2][4];
            #pragma unroll
            for (int mi = 0; mi < 4; mi++)
                ldsm_x4(ah[mi], aB + (uint32_t)(mi * 16 * GSTRIDE * 2) + kb);
            #pragma unroll
            for (int p = 0; p < 2; p++)
                ldsm_x4(bh[p], bB + (uint32_t)(p * 16 * GSTRIDE * 2) + kb);
            #pragma unroll
            for (int mi = 0; mi < 4; mi++) {
                #pragma unroll
                for (int nj = 0; nj < 4; nj++) {
                    const int p = nj >> 1, s = (nj & 1) * 2;
                    mma16816h(c[mi][nj], ah[mi], bh[p][s], bh[p][s + 1]);
                }
            }
        }
        __syncthreads();
    }

    #pragma unroll
    for (int mi = 0; mi < 4; mi++) {
        int r0 = m0 + wm + mi * 16 + (l >> 2);
        #pragma unroll
        for (int nj = 0; nj < 4; nj++) {
            int col = n0 + wn + nj * 8 + (l & 3) * 2;
            float b0 = bias[col], b1 = bias[col + 1];
            #pragma unroll
            for (int half = 0; half < 2; half++) {
                int r = r0 + half * 8;
                float v0 = c[mi][nj][half * 2 + 0] + b0;
                float v1 = c[mi][nj][half * 2 + 1] + b1;
                *(__half2*)(Ch + (size_t)r * ldch + col) =
                    __halves2half2(__float2half(v0), __float2half(v1));
            }
        }
    }
}

// ================= fused FFN: out = sigmoid(cat@W1+b1) * (cat@W2+b2) =================
#define E3STG (3 * GBUF)

__global__ __launch_bounds__(256) void gemm_ffn(
    const __half* __restrict__ A, const __half* __restrict__ B1,
    const __half* __restrict__ B2,
    const float* __restrict__ b1p, const float* __restrict__ b2p,
    float* __restrict__ Cf)
{
    extern __shared__ __half smh[];
    const int tid = threadIdx.x;
    const int w = tid >> 5, l = tid & 31;
    const int m0 = blockIdx.y * 128;
    const int n0 = blockIdx.x * 128;
    const int wm = (w >> 2) * 64;
    const int wn = (w & 3) * 32;
    const int Kdim = 2 * HID;

    float c1[4][4][4], c2[4][4][4];
    #pragma unroll
    for (int i = 0; i < 4; i++)
        #pragma unroll
        for (int j = 0; j < 4; j++)
            #pragma unroll
            for (int q = 0; q < 4; q++) { c1[i][j][q] = 0.f; c2[i][j][q] = 0.f; }

    const uint32_t sbase = smem_u32(smh);
    const int aRow = wm + (l & 15), aKof = (l >> 4) * 8;
    const int bRow = wn + (l >> 4) * 8 + (l & 7), bKof = ((l >> 3) & 1) * 8;
    const int nChunks = Kdim >> 6;   // 24

    auto issue = [&](int ch) {
        const uint32_t dstBase = sbase + (uint32_t)((ch & 1) * E3STG * 2);
        const int k0 = ch << 6;
        #pragma unroll
        for (int i = 0; i < 4; i++) {
            int t = tid + i * 256;
            int row = t >> 3, c8 = (t & 7) * 8;
            uint32_t d = dstBase + (uint32_t)((row * GSTRIDE + c8) * 2);
            cp16(d,                A  + (size_t)(m0 + row) * Kdim + k0 + c8);
            cp16(d + GBUF * 2,     B1 + (size_t)(n0 + row) * Kdim + k0 + c8);
            cp16(d + 2 * GBUF * 2, B2 + (size_t)(n0 + row) * Kdim + k0 + c8);
        }
    };

    issue(0); CP_COMMIT();
    for (int ch = 0; ch < nChunks; ch++) {
        CP_WAIT0();
        __syncthreads();
        if (ch + 1 < nChunks) { issue(ch + 1); CP_COMMIT(); }

        const uint32_t sb = sbase + (uint32_t)((ch & 1) * E3STG * 2);
        const uint32_t aB  = sb + (uint32_t)((aRow * GSTRIDE + aKof) * 2);
        const uint32_t b1B = sb + GBUF * 2 + (uint32_t)((bRow * GSTRIDE + bKof) * 2);
        const uint32_t b2B = b1B + GBUF * 2;

        #pragma unroll
        for (int ks = 0; ks < 4; ks++) {
            const uint32_t kb = (uint32_t)(ks * 16 * 2);
            uint32_t ah[4][4], bh1[2][4], bh2[2][4];
            #pragma unroll
            for (int mi = 0; mi < 4; mi++)
                ldsm_x4(ah[mi], aB + (uint32_t)(mi * 16 * GSTRIDE * 2) + kb);
            #pragma unroll
            for (int p = 0; p < 2; p++) {
                ldsm_x4(bh1[p], b1B + (uint32_t)(p * 16 * GSTRIDE * 2) + kb);
                ldsm_x4(bh2[p], b2B + (uint32_t)(p * 16 * GSTRIDE * 2) + kb);
            }
            #pragma unroll
            for (int mi = 0; mi < 4; mi++) {
                #pragma unroll
                for (int nj = 0; nj < 4; nj++) {
                    const int p = nj >> 1, s = (nj & 1) * 2;
                    mma16816h(c1[mi][nj], ah[mi], bh1[p][s], bh1[p][s + 1]);
                    mma16816h(c2[mi][nj], ah[mi], bh2[p][s], bh2[p][s + 1]);
                }
            }
        }
        __syncthreads();
    }

    #pragma unroll
    for (int mi = 0; mi < 4; mi++) {
        int r0 = m0 + wm + mi * 16 + (l >> 2);
        #pragma unroll
        for (int nj = 0; nj < 4; nj++) {
            int col = n0 + wn + nj * 8 + (l & 3) * 2;
            float bb1a = b1p[col], bb1b = b1p[col + 1];
            float bb2a = b2p[col], bb2b = b2p[col + 1];
            #pragma unroll
            for (int half = 0; half < 2; half++) {
                int r = r0 + half * 8;
                float g0 = c1[mi][nj][half * 2 + 0] + bb1a;
                float g1 = c1[mi][nj][half * 2 + 1] + bb1b;
                float v0 = c2[mi][nj][half * 2 + 0] + bb2a;
                float v1 = c2[mi][nj][half * 2 + 1] + bb2b;
                v0 *= 1.f / (1.f + __expf(-g0));
                v1 *= 1.f / (1.f + __expf(-g1));
                *(float2*)(Cf + (size_t)r * HID + col) = make_float2(v0, v1);
            }
        }
    }
}

// ================= attention v8: R13 structure + register row sums + f4 prob stores =================
// smem bytes:
//   sQ  [0, 9216)                 : 64 x 72 fp16
//   stages 2 x 36864 [9216, 82944): per stage: K 128x72 + V 128x72
//   sE  [82944, 215040)           : 64 x 1032 fp16 (unnormalized e, for prob output)
//   sMask [215040, 219136)        : 1024 int
//   sInv  [219136, 219392)        : 64 float
//   sSum  [219392, 219648)        : 64 float
//   sPart overlays stage region after main loop
#define EST 1032
#define KVST 72
#define CSTG 18432
#define ASTG 36864
#define ATTN_SMEM 219648

__global__ __launch_bounds__(512) void attn_mma(
    const __half* __restrict__ qf, const __half* __restrict__ kpf,
    const __half* __restrict__ vpf,
    const int* __restrict__ mask, float* __restrict__ attn_out,
    __half* __restrict__ xf)
{
    extern __shared__ char sab[];
    __half* sQ = (__half*)(sab);
    __half* sE = (__half*)(sab + 82944);
    int*   sMask = (int*)(sab + 215040);
    float* sInv  = (float*)(sab + 219136);
    float* sSum  = (float*)(sab + 219392);
    float* sPart = (float*)(sab + 9216);

    const int tid = threadIdx.x, w = tid >> 5, l = tid & 31;
    const int q0 = blockIdx.x * 64, h = blockIdx.y, b = blockIdx.z;

    const uint32_t uQ  = smem_u32(sab);
    const uint32_t uK0 = uQ + 9216;

    // load Q tile (64 x 64 fp16) + mask + zero sums
    {
        int r = tid >> 3, c8 = (tid & 7) * 8;
        size_t g = ((size_t)(b * SS + q0 + r)) * HID + h * HD + c8;
        *(uint4*)(sQ + r * KVST + c8) = *(const uint4*)(qf + g);
    }
    for (int k = tid; k < SS; k += 512) sMask[k] = mask[b * SS + k];
    if (tid < 64) sSum[tid] = 0.f;

    const int mg = w & 3;           // 16-query row group
    const int sub = w >> 2;         // 32-key slice within 128-key chunk
    const int bRowL = (l >> 4) * 8 + (l & 7);
    const int bKofL = ((l >> 3) & 1) * 8;
    const uint32_t aLaneOff = (uint32_t)(((mg * 16 + (l & 15)) * KVST + (l >> 4) * 8) * 2);

    // issue one 128-key chunk (K + V) into stage st
    auto issueKV = [&](int chunk, int st) {
        const uint32_t dst = uK0 + (uint32_t)(st * ASTG);
        const int r0 = chunk * 128;
        #pragma unroll
        for (int i = 0; i < 2; i++) {
            int t = tid + i * 512;
            int row = t >> 3, c8 = (t & 7) * 8;
            uint32_t d = dst + (uint32_t)((row * KVST + c8) * 2);
            size_t g = ((size_t)(b * SS + r0 + row)) * HID + h * HD + c8;
            cp16(d,        kpf + g);
            cp16(d + CSTG, vpf + g);
        }
    };

    // x accumulator: 16q x 64d per warp (this warp's key slice)
    float xa[8][4];
    #pragma unroll
    for (int j = 0; j < 8; j++)
        #pragma unroll
        for (int q = 0; q < 4; q++) xa[j][q] = 0.f;

    float s_lo = 0.f, s_hi = 0.f;   // row sums for rows mg*16+(l>>2) and +8

    // ---------- main loop: 8 chunks x 128 keys; QK -> exp -> (sE store + inline PV) ----------
    issueKV(0, 0); CP_COMMIT();
    for (int ch = 0; ch < 8; ch++) {
        CP_WAIT0();
        __syncthreads();
        if (ch < 7) { issueKV(ch + 1, (ch + 1) & 1); CP_COMMIT(); }

        const uint32_t sbK = uK0 + (uint32_t)((ch & 1) * ASTG);
        const uint32_t sbV = sbK + CSTG;
        const int kw0 = ch * 128 + sub * 32;

        // --- QK^T for this warp's 16q x 32k slice ---
        float ea[2][2][4];
        #pragma unroll
        for (int p = 0; p < 2; p++)
            #pragma unroll
            for (int t = 0; t < 2; t++)
                #pragma unroll
                for (int q = 0; q < 4; q++) ea[p][t][q] = 0.f;

        #pragma unroll
        for (int ks = 0; ks < 4; ks++) {
            uint32_t ah[4], bk[2][4];
            ldsm_x4(ah, uQ + aLaneOff + (uint32_t)(ks * 16 * 2));
            #pragma unroll
            for (int p = 0; p < 2; p++)
                ldsm_x4(bk[p], sbK + (uint32_t)(((sub * 32 + p * 16 + bRowL) * KVST + ks * 16 + bKofL) * 2));
            #pragma unroll
            for (int p = 0; p < 2; p++) {
                #pragma unroll
                for (int t = 0; t < 2; t++)
                    mma16816h(ea[p][t], ah, bk[p][t * 2], bk[p][t * 2 + 1]);
            }
        }

        // --- epilogue: mask + exp; store to sE, accumulate sums, pack A-fragments ---
        uint32_t aF[2][4];
        #pragma unroll
        for (int p = 0; p < 2; p++) {
            #pragma unroll
            for (int t = 0; t < 2; t++) {
                int kcol = kw0 + p * 16 + t * 8 + (l & 3) * 2;
                int mk0 = sMask[kcol], mk1 = sMask[kcol + 1];
                #pragma unroll
                for (int hf = 0; hf < 2; hf++) {
                    int row = mg * 16 + (l >> 2) + hf * 8;
                    float e0 = mk0 ? __expf(fminf(ea[p][t][hf * 2 + 0], 11.f)) : 0.f;
                    float e1 = mk1 ? __expf(fminf(ea[p][t][hf * 2 + 1], 11.f)) : 0.f;
                    if (hf == 0) s_lo += e0 + e1; else s_hi += e0 + e1;
                    __half2 h2 = __halves2half2(__float2half(e0), __float2half(e1));
                    *(__half2*)(sE + row * EST + kcol) = h2;
                    aF[p][t * 2 + hf] = *(uint32_t*)&h2;
                }
            }
        }

        // --- inline PV: xa += e_chunk @ V_chunk (16q x 32k x 64d) ---
        #pragma unroll
        for (int p = 0; p < 2; p++) {
            #pragma unroll
            for (int dt = 0; dt < 4; dt++) {
                uint32_t bv[4];
                ldsm_x4_t(bv, sbV + (uint32_t)(((sub * 32 + p * 16 + (l & 15)) * KVST + dt * 16 + (l >> 4) * 8) * 2));
                mma16816h(xa[dt * 2 + 0], aF[p], bv[0], bv[1]);
                mma16816h(xa[dt * 2 + 1], aF[p], bv[2], bv[3]);
            }
        }
    }

    // ---------- reduce row sums (quad shfl + smem atomics) ----------
    #pragma unroll
    for (int o = 1; o < 4; o <<= 1) {
        s_lo += __shfl_xor_sync(0xffffffffu, s_lo, o);
        s_hi += __shfl_xor_sync(0xffffffffu, s_hi, o);
    }
    if ((l & 3) == 0) {
        atomicAdd(&sSum[mg * 16 + (l >> 2)], s_lo);
        atomicAdd(&sSum[mg * 16 + (l >> 2) + 8], s_hi);
    }
    __syncthreads();
    if (tid < 64) sInv[tid] = 1.f / sSum[tid];
    __syncthreads();

    // ---------- Phase B: scale + write probs (float4 stores) ----------
    #pragma unroll
    for (int r = w * 4; r < w * 4 + 4; r++) {
        const __half* eh = sE + r * EST;
        const float inv = sInv[r];
        float* orow = attn_out + ((size_t)((b * NH + h) * SS + q0 + r)) * SS;
        #pragma unroll
        for (int i = 0; i < 8; i++) {
            int col = i * 128 + l * 4;
            __half2 a = *(const __half2*)(eh + col);
            __half2 bb = *(const __half2*)(eh + col + 2);
            float4 v = make_float4(__half2float(a.x) * inv, __half2float(a.y) * inv,
                                   __half2float(bb.x) * inv, __half2float(bb.y) * inv);
            *(float4*)(orow + col) = v;
        }
    }
    __syncthreads();

    // ---------- x reduction over 4 key-slices (sub) via smem overlay ----------
    if (sub > 0) {
        float* dst = sPart + (sub - 1) * 4096;
        #pragma unroll
        for (int j = 0; j < 8; j++)
            #pragma unroll
            for (int v = 0; v < 4; v++) {
                int row = mg * 16 + (l >> 2) + (v >> 1) * 8;
                int col = (j >> 1) * 16 + (j & 1) * 8 + (l & 3) * 2 + (v & 1);
                dst[row * 64 + col] = xa[j][v];
            }
    }
    __syncthreads();
    if (sub == 0) {
        #pragma unroll
        for (int j = 0; j < 8; j++) {
            #pragma unroll
            for (int hf = 0; hf < 2; hf++) {
                int row = mg * 16 + (l >> 2) + hf * 8;
                int col = (j >> 1) * 16 + (j & 1) * 8 + (l & 3) * 2;
                float inv = sInv[row];
                float x0 = xa[j][hf * 2 + 0];
                float x1 = xa[j][hf * 2 + 1];
                #pragma unroll
                for (int p = 0; p < 3; p++) {
                    x0 += sPart[p * 4096 + row * 64 + col];
                    x1 += sPart[p * 4096 + row * 64 + col + 1];
                }
                x0 *= inv; x1 *= inv;
                size_t g = ((size_t)(b * SS + q0 + row)) * HID + h * HD + col;
                *(__half2*)(xf + g) = __halves2half2(__float2half(x0), __float2half(x1));
            }
        }
    }
}

// ================= launch =================
extern "C" void kernel_launch(void* const* d_in, const int* in_sizes, int n_in,
                              void* d_out, int out_size)
{
    const float* query = (const float*)d_in[0];
    const float* key_t = (const float*)d_in[1];
    const float* value = (const float*)d_in[2];
    const int*   mask  = (const int*)d_in[3];
    const float* Wq = (const float*)d_in[4];  const float* bq = (const float*)d_in[5];
    const float* Wk = (const float*)d_in[6];  const float* bk = (const float*)d_in[7];
    const float* Wv = (const float*)d_in[8];  const float* bv = (const float*)d_in[9];
    const float* Wo = (const float*)d_in[10]; const float* bo = (const float*)d_in[11];
    const float* W1 = (const float*)d_in[12]; const float* b1 = (const float*)d_in[13];
    const float* W2 = (const float*)d_in[14]; const float* b2 = (const float*)d_in[15];

    float* out       = (float*)d_out;
    float* out_gated = out;
    float* out_attn  = out + MH;

    __half *kf, *vf, *qfp, *kpf, *vpf, *xf, *cat, *wqk, *wfo, *wf;
    cudaGetSymbolAddress((void**)&kf, g_kf);
    cudaGetSymbolAddress((void**)&vf, g_vf);
    cudaGetSymbolAddress((void**)&qfp, g_qf);
    cudaGetSymbolAddress((void**)&kpf, g_kpf);
    cudaGetSymbolAddress((void**)&vpf, g_vpf);
    cudaGetSymbolAddress((void**)&xf, g_xf);
    cudaGetSymbolAddress((void**)&cat, g_cat);
    cudaGetSymbolAddress((void**)&wqk, g_wqk);
    cudaGetSymbolAddress((void**)&wfo, g_wfo);
    cudaGetSymbolAddress((void**)&wf, g_wf);

    size_t fsmem = (size_t)2 * FSTAGE * 2;   // 73728 B
    size_t esmem = (size_t)2 * E3STG * 2;    // 110592 B
    cudaFuncSetAttribute(gemm_qkv, cudaFuncAttributeMaxDynamicSharedMemorySize, (int)fsmem);
    cudaFuncSetAttribute(gemm_fp16, cudaFuncAttributeMaxDynamicSharedMemorySize, (int)fsmem);
    cudaFuncSetAttribute(gemm_ffn, cudaFuncAttributeMaxDynamicSharedMemorySize, (int)esmem);
    cudaFuncSetAttribute(attn_mma, cudaFuncAttributeMaxDynamicSharedMemorySize, ATTN_SMEM);

    const int actBlocks = (MROWS * HID / 4 + 255) / 256;
    dim3 wblk(32, 8);
    dim3 ggrid(HID / 128, MROWS / 128);      // (6, 64)

    // --- input conversions + weight splits ---
    conv3<<<dim3(actBlocks, 3), 256>>>(query, key_t, value, cat, kf, vf);
    split_wqk3<<<dim3(HID / 32, HID / 32, 3), wblk>>>(Wq, Wk, Wv, wqk);

    // --- QKV projections (fp16 single-term; Q pre-scaled 1/8) ---
    gemm_qkv<<<dim3(HID / 128, MROWS / 128, 3), 256, fsmem>>>(
        cat + HID, kf, vf, wqk, bq, bk, bv, qfp, kpf, vpf);

    // --- attention (flash-style inline PV + register sums) ---
    attn_mma<<<dim3(SS / 64, NH, BB), 512, ATTN_SMEM>>>(
        qfp, kpf, vpf, mask, out_attn, xf);

    // --- Wo (fp16) -> cat[:, 0:768] ---
    split_w_fp16<<<dim3(HID / 32, HID / 32), wblk>>>(Wo, HID, HID, wfo);
    gemm_fp16<<<ggrid, 256, fsmem>>>(
        xf, HID, wfo, HID, bo, cat, 2 * HID);

    // --- fused FFN (fp16, K=1536): out = sigmoid(cat@W1+b1) * (cat@W2+b2) ---
    split_wf2<<<dim3(HID / 32, 2 * HID / 32, 2), wblk>>>(W1, W2, wf);
    gemm_ffn<<<ggrid, 256, esmem>>>(
        cat, wf, wf + (size_t)2 * HID * HID, b1, b2, out_gated);
}

// round 16
// speedup vs baseline: 1.1413x; 1.0343x over previous
#include <cuda_runtime.h>
#include <cuda_fp16.h>
#include <math.h>
#include <stdint.h>

#define BB 8
#define SS 1024
#define HID 768
#define NH 12
#define HD 64
#define MROWS (BB*SS)   // 8192
#define MH ((size_t)MROWS*HID)

// ---------------- scratch (device globals; no allocation allowed) ----------------
__device__ __align__(256) __half g_kf [MH];                     // raw key fp16
__device__ __align__(256) __half g_vf [MH];                     // raw value fp16
__device__ __align__(256) __half g_qf [MH];                     // projected Q (fp16, prescaled)
__device__ __align__(256) __half g_kpf[MH];                     // projected K (fp16)
__device__ __align__(256) __half g_vpf[MH];                     // projected V (fp16)

__device__ __align__(256) __half g_xf [MH];
__device__ __align__(256) __half g_cat[2*MH];
__device__ __align__(256) __half g_wqk[(size_t)3*HID*HID];      // Wq,Wk,Wv fp16 [N][K]
__device__ __align__(256) __half g_wfo[(size_t)HID*HID];
__device__ __align__(256) __half g_wf [(size_t)2*2*HID*HID];    // W1,W2 fp16 [N][K]

// ================= helpers =================
__device__ __forceinline__ uint32_t smem_u32(const void* p) {
    uint32_t a;
    asm("{ .reg .u64 t; cvta.to.shared.u64 t, %1; cvt.u32.u64 %0, t; }" : "=r"(a) : "l"(p));
    return a;
}
__device__ __forceinline__ void ldsm_x4(uint32_t* r, uint32_t addr) {
    asm volatile("ldmatrix.sync.aligned.m8n8.x4.shared.b16 {%0,%1,%2,%3}, [%4];"
                 : "=r"(r[0]), "=r"(r[1]), "=r"(r[2]), "=r"(r[3]) : "r"(addr));
}
__device__ __forceinline__ void ldsm_x4_t(uint32_t* r, uint32_t addr) {
    asm volatile("ldmatrix.sync.aligned.m8n8.x4.trans.shared.b16 {%0,%1,%2,%3}, [%4];"
                 : "=r"(r[0]), "=r"(r[1]), "=r"(r[2]), "=r"(r[3]) : "r"(addr));
}
__device__ __forceinline__ void mma16816h(float* c, const uint32_t* a, uint32_t b0, uint32_t b1) {
    asm volatile("mma.sync.aligned.m16n8k16.row.col.f32.f16.f16.f32 "
                 "{%0,%1,%2,%3}, {%4,%5,%6,%7}, {%8,%9}, {%0,%1,%2,%3};"
                 : "+f"(c[0]), "+f"(c[1]), "+f"(c[2]), "+f"(c[3])
                 : "r"(a[0]), "r"(a[1]), "r"(a[2]), "r"(a[3]), "r"(b0), "r"(b1));
}
__device__ __forceinline__ void cp16(uint32_t dst, const void* src) {
    asm volatile("cp.async.cg.shared.global [%0], [%1], 16;" :: "r"(dst), "l"(src));
}
#define CP_COMMIT() asm volatile("cp.async.commit_group;" ::: "memory")
#define CP_WAIT0()  asm volatile("cp.async.wait_group 0;" ::: "memory")

// ================= convert / weight-split kernels =================
__global__ void conv3(const float* __restrict__ q, const float* __restrict__ k,
                      const float* __restrict__ v,
                      __half* __restrict__ cat, __half* __restrict__ kf,
                      __half* __restrict__ vf)
{
    const int z = blockIdx.y;
    const float* src = (z == 0) ? q : (z == 1) ? k : v;
    size_t total = MH / 4;
    for (size_t i = (size_t)blockIdx.x * blockDim.x + threadIdx.x; i < total;
         i += (size_t)gridDim.x * blockDim.x) {
        size_t e = i * 4;
        int m = (int)(e / HID), c = (int)(e % HID);
        float4 x = *(const float4*)(src + e);
        __half* dst = (z == 0) ? (cat + (size_t)m * (2 * HID) + HID + c)
                    : (z == 1) ? (kf + e) : (vf + e);
        *(__half2*)(dst)     = __halves2half2(__float2half(x.x), __float2half(x.y));
        *(__half2*)(dst + 2) = __halves2half2(__float2half(x.z), __float2half(x.w));
    }
}

__global__ void split_wqk3(const float* __restrict__ Wa, const float* __restrict__ Wb,
                           const float* __restrict__ Wc, __half* __restrict__ out)
{
    __shared__ float t[32][33];
    const int z = blockIdx.z;
    const float* W = (z == 0) ? Wa : (z == 1) ? Wb : Wc;
    __half* O = out + (size_t)z * HID * HID;
    int n0 = blockIdx.x * 32, k0 = blockIdx.y * 32;
    int tx = threadIdx.x, ty = threadIdx.y;
    for (int j = ty; j < 32; j += 8)
        t[j][tx] = W[(size_t)(k0 + j) * HID + n0 + tx];
    __syncthreads();
    for (int j = ty; j < 32; j += 8)
        O[(size_t)(n0 + j) * HID + k0 + tx] = __float2half(t[tx][j]);
}

__global__ void split_w_fp16(const float* __restrict__ W, int K, int N,
                             __half* __restrict__ out)
{
    __shared__ float t[32][33];
    int n0 = blockIdx.x * 32, k0 = blockIdx.y * 32;
    int tx = threadIdx.x, ty = threadIdx.y;
    for (int j = ty; j < 32; j += 8)
        t[j][tx] = W[(size_t)(k0 + j) * N + n0 + tx];
    __syncthreads();
    for (int j = ty; j < 32; j += 8)
        out[(size_t)(n0 + j) * K + k0 + tx] = __float2half(t[tx][j]);
}

__global__ void split_wf2(const float* __restrict__ Wa, const float* __restrict__ Wb,
                          __half* __restrict__ out)
{
    __shared__ float t[32][33];
    const int z = blockIdx.z;
    const float* W = (z == 0) ? Wa : Wb;
    __half* O = out + (size_t)z * 2 * HID * HID;
    int n0 = blockIdx.x * 32, k0 = blockIdx.y * 32;
    int tx = threadIdx.x, ty = threadIdx.y;
    for (int j = ty; j < 32; j += 8)
        t[j][tx] = W[(size_t)(k0 + j) * HID + n0 + tx];
    __syncthreads();
    for (int j = ty; j < 32; j += 8)
        O[(size_t)(n0 + j) * (2 * HID) + k0 + tx] = __float2half(t[tx][j]);
}

// ================= fp16 QKV projection GEMM (batched z = 0,1,2) =================
#define GSTRIDE 72
#define GBUF (128 * GSTRIDE)
#define FSTAGE (2 * GBUF)

__global__ __launch_bounds__(256) void gemm_qkv(
    const __half* __restrict__ Aq, const __half* __restrict__ Ak,
    const __half* __restrict__ Av, const __half* __restrict__ Bw,
    const float* __restrict__ bq, const float* __restrict__ bk,
    const float* __restrict__ bv,
    __half* __restrict__ oq, __half* __restrict__ ok, __half* __restrict__ ov)
{
    extern __shared__ __half smh[];
    const int tid = threadIdx.x;
    const int w = tid >> 5, l = tid & 31;
    const int z = blockIdx.z;
    const int m0 = blockIdx.y * 128;
    const int n0 = blockIdx.x * 128;
    const int wm = (w >> 2) * 64;
    const int wn = (w & 3) * 32;

    const __half* A = (z == 0) ? Aq : (z == 1) ? Ak : Av;
    const int lda = (z == 0) ? 2 * HID : HID;
    const __half* B = Bw + (size_t)z * HID * HID;
    const float* bias = (z == 0) ? bq : (z == 1) ? bk : bv;
    const float scale = (z == 0) ? 0.125f : 1.f;
    __half* out = (z == 0) ? oq : (z == 1) ? ok : ov;

    float c[4][4][4];
    #pragma unroll
    for (int i = 0; i < 4; i++)
        #pragma unroll
        for (int j = 0; j < 4; j++)
            #pragma unroll
            for (int q = 0; q < 4; q++) c[i][j][q] = 0.f;

    const uint32_t sbase = smem_u32(smh);
    const int aRow = wm + (l & 15), aKof = (l >> 4) * 8;
    const int bRow = wn + (l >> 4) * 8 + (l & 7), bKof = ((l >> 3) & 1) * 8;
    const int nChunks = HID >> 6;

    auto issue = [&](int ch) {
        const uint32_t dstBase = sbase + (uint32_t)((ch & 1) * FSTAGE * 2);
        const int k0 = ch << 6;
        #pragma unroll
        for (int i = 0; i < 4; i++) {
            int t = tid + i * 256;
            int row = t >> 3, c8 = (t & 7) * 8;
            uint32_t d = dstBase + (uint32_t)((row * GSTRIDE + c8) * 2);
            cp16(d,            A + (size_t)(m0 + row) * lda + k0 + c8);
            cp16(d + GBUF * 2, B + (size_t)(n0 + row) * HID + k0 + c8);
        }
    };

    issue(0); CP_COMMIT();
    for (int ch = 0; ch < nChunks; ch++) {
        CP_WAIT0();
        __syncthreads();
        if (ch + 1 < nChunks) { issue(ch + 1); CP_COMMIT(); }

        const uint32_t sb = sbase + (uint32_t)((ch & 1) * FSTAGE * 2);
        const uint32_t aB = sb + (uint32_t)((aRow * GSTRIDE + aKof) * 2);
        const uint32_t bB = sb + GBUF * 2 + (uint32_t)((bRow * GSTRIDE + bKof) * 2);

        #pragma unroll
        for (int ks = 0; ks < 4; ks++) {
            const uint32_t kb = (uint32_t)(ks * 16 * 2);
            uint32_t ah[4][4], bh[2][4];
            #pragma unroll
            for (int mi = 0; mi < 4; mi++)
                ldsm_x4(ah[mi], aB + (uint32_t)(mi * 16 * GSTRIDE * 2) + kb);
            #pragma unroll
            for (int p = 0; p < 2; p++)
                ldsm_x4(bh[p], bB + (uint32_t)(p * 16 * GSTRIDE * 2) + kb);
            #pragma unroll
            for (int mi = 0; mi < 4; mi++) {
                #pragma unroll
                for (int nj = 0; nj < 4; nj++) {
                    const int p = nj >> 1, s = (nj & 1) * 2;
                    mma16816h(c[mi][nj], ah[mi], bh[p][s], bh[p][s + 1]);
                }
            }
        }
        __syncthreads();
    }

    #pragma unroll
    for (int mi = 0; mi < 4; mi++) {
        int r0 = m0 + wm + mi * 16 + (l >> 2);
        #pragma unroll
        for (int nj = 0; nj < 4; nj++) {
            int col = n0 + wn + nj * 8 + (l & 3) * 2;
            float b0 = bias[col], b1 = bias[col + 1];
            #pragma unroll
            for (int half = 0; half < 2; half++) {
                int r = r0 + half * 8;
                float v0 = (c[mi][nj][half * 2 + 0] + b0) * scale;
                float v1 = (c[mi][nj][half * 2 + 1] + b1) * scale;
                *(__half2*)(out + (size_t)r * HID + col) =
                    __halves2half2(__float2half(v0), __float2half(v1));
            }
        }
    }
}

// ================= fp16 single-term GEMM (Wo) =================
__global__ __launch_bounds__(256) void gemm_fp16(
    const __half* __restrict__ A, int lda, const __half* __restrict__ B,
    int Kdim, const float* __restrict__ bias,
    __half* __restrict__ Ch, int ldch)
{
    extern __shared__ __half smh[];
    const int tid = threadIdx.x;
    const int w = tid >> 5, l = tid & 31;
    const int m0 = blockIdx.y * 128;
    const int n0 = blockIdx.x * 128;
    const int wm = (w >> 2) * 64;
    const int wn = (w & 3) * 32;

    float c[4][4][4];
    #pragma unroll
    for (int i = 0; i < 4; i++)
        #pragma unroll
        for (int j = 0; j < 4; j++)
            #pragma unroll
            for (int q = 0; q < 4; q++) c[i][j][q] = 0.f;

    const uint32_t sbase = smem_u32(smh);
    const int aRow = wm + (l & 15), aKof = (l >> 4) * 8;
    const int bRow = wn + (l >> 4) * 8 + (l & 7), bKof = ((l >> 3) & 1) * 8;
    const int nChunks = Kdim >> 6;

    auto issue = [&](int ch) {
        const uint32_t dstBase = sbase + (uint32_t)((ch & 1) * FSTAGE * 2);
        const int k0 = ch << 6;
        #pragma unroll
        for (int i = 0; i < 4; i++) {
            int t = tid + i * 256;
            int row = t >> 3, c8 = (t & 7) * 8;
            uint32_t d = dstBase + (uint32_t)((row * GSTRIDE + c8) * 2);
            cp16(d,            A + (size_t)(m0 + row) * lda  + k0 + c8);
            cp16(d + GBUF * 2, B + (size_t)(n0 + row) * Kdim + k0 + c8);
        }
    };

    issue(0); CP_COMMIT();
    for (int ch = 0; ch < nChunks; ch++) {
        CP_WAIT0();
        __syncthreads();
        if (ch + 1 < nChunks) { issue(ch + 1); CP_COMMIT(); }

        const uint32_t sb = sbase + (uint32_t)((ch & 1) * FSTAGE * 2);
        const uint32_t aB = sb + (uint32_t)((aRow * GSTRIDE + aKof) * 2);
        const uint32_t bB = sb + GBUF * 2 + (uint32_t)((bRow * GSTRIDE + bKof) * 2);

        #pragma unroll
        for (int ks = 0; ks < 4; ks++) {
            const uint32_t kb = (uint32_t)(ks * 16 * 2);
            uint32_t ah[4][4], bh[2][4];
            #pragma unroll
            for (int mi = 0; mi < 4; mi++)
                ldsm_x4(ah[mi], aB + (uint32_t)(mi * 16 * GSTRIDE * 2) + kb);
            #pragma unroll
            for (int p = 0; p < 2; p++)
                ldsm_x4(bh[p], bB + (uint32_t)(p * 16 * GSTRIDE * 2) + kb);
            #pragma unroll
            for (int mi = 0; mi < 4; mi++) {
                #pragma unroll
                for (int nj = 0; nj < 4; nj++) {
                    const int p = nj >> 1, s = (nj & 1) * 2;
                    mma16816h(c[mi][nj], ah[mi], bh[p][s], bh[p][s + 1]);
                }
            }
        }
        __syncthreads();
    }

    #pragma unroll
    for (int mi = 0; mi < 4; mi++) {
        int r0 = m0 + wm + mi * 16 + (l >> 2);
        #pragma unroll
        for (int nj = 0; nj < 4; nj++) {
            int col = n0 + wn + nj * 8 + (l & 3) * 2;
            float b0 = bias[col], b1 = bias[col + 1];
            #pragma unroll
            for (int half = 0; half < 2; half++) {
                int r = r0 + half * 8;
                float v0 = c[mi][nj][half * 2 + 0] + b0;
                float v1 = c[mi][nj][half * 2 + 1] + b1;
                *(__half2*)(Ch + (size_t)r * ldch + col) =
                    __halves2half2(__float2half(v0), __float2half(v1));
            }
        }
    }
}

// ================= fused FFN: out = sigmoid(cat@W1+b1) * (cat@W2+b2) =================
#define E3STG (3 * GBUF)

__global__ __launch_bounds__(256) void gemm_ffn(
    const __half* __restrict__ A, const __half* __restrict__ B1,
    const __half* __restrict__ B2,
    const float* __restrict__ b1p, const float* __restrict__ b2p,
    float* __restrict__ Cf)
{
    extern __shared__ __half smh[];
    const int tid = threadIdx.x;
    const int w = tid >> 5, l = tid & 31;
    const int m0 = blockIdx.y * 128;
    const int n0 = blockIdx.x * 128;
    const int wm = (w >> 2) * 64;
    const int wn = (w & 3) * 32;
    const int Kdim = 2 * HID;

    float c1[4][4][4], c2[4][4][4];
    #pragma unroll
    for (int i = 0; i < 4; i++)
        #pragma unroll
        for (int j = 0; j < 4; j++)
            #pragma unroll
            for (int q = 0; q < 4; q++) { c1[i][j][q] = 0.f; c2[i][j][q] = 0.f; }

    const uint32_t sbase = smem_u32(smh);
    const int aRow = wm + (l & 15), aKof = (l >> 4) * 8;
    const int bRow = wn + (l >> 4) * 8 + (l & 7), bKof = ((l >> 3) & 1) * 8;
    const int nChunks = Kdim >> 6;   // 24

    auto issue = [&](int ch) {
        const uint32_t dstBase = sbase + (uint32_t)((ch & 1) * E3STG * 2);
        const int k0 = ch << 6;
        #pragma unroll
        for (int i = 0; i < 4; i++) {
            int t = tid + i * 256;
            int row = t >> 3, c8 = (t & 7) * 8;
            uint32_t d = dstBase + (uint32_t)((row * GSTRIDE + c8) * 2);
            cp16(d,                A  + (size_t)(m0 + row) * Kdim + k0 + c8);
            cp16(d + GBUF * 2,     B1 + (size_t)(n0 + row) * Kdim + k0 + c8);
            cp16(d + 2 * GBUF * 2, B2 + (size_t)(n0 + row) * Kdim + k0 + c8);
        }
    };

    issue(0); CP_COMMIT();
    for (int ch = 0; ch < nChunks; ch++) {
        CP_WAIT0();
        __syncthreads();
        if (ch + 1 < nChunks) { issue(ch + 1); CP_COMMIT(); }

        const uint32_t sb = sbase + (uint32_t)((ch & 1) * E3STG * 2);
        const uint32_t aB  = sb + (uint32_t)((aRow * GSTRIDE + aKof) * 2);
        const uint32_t b1B = sb + GBUF * 2 + (uint32_t)((bRow * GSTRIDE + bKof) * 2);
        const uint32_t b2B = b1B + GBUF * 2;

        #pragma unroll
        for (int ks = 0; ks < 4; ks++) {
            const uint32_t kb = (uint32_t)(ks * 16 * 2);
            uint32_t ah[4][4], bh1[2][4], bh2[2][4];
            #pragma unroll
            for (int mi = 0; mi < 4; mi++)
                ldsm_x4(ah[mi], aB + (uint32_t)(mi * 16 * GSTRIDE * 2) + kb);
            #pragma unroll
            for (int p = 0; p < 2; p++) {
                ldsm_x4(bh1[p], b1B + (uint32_t)(p * 16 * GSTRIDE * 2) + kb);
                ldsm_x4(bh2[p], b2B + (uint32_t)(p * 16 * GSTRIDE * 2) + kb);
            }
            #pragma unroll
            for (int mi = 0; mi < 4; mi++) {
                #pragma unroll
                for (int nj = 0; nj < 4; nj++) {
                    const int p = nj >> 1, s = (nj & 1) * 2;
                    mma16816h(c1[mi][nj], ah[mi], bh1[p][s], bh1[p][s + 1]);
                    mma16816h(c2[mi][nj], ah[mi], bh2[p][s], bh2[p][s + 1]);
                }
            }
        }
        __syncthreads();
    }

    #pragma unroll
    for (int mi = 0; mi < 4; mi++) {
        int r0 = m0 + wm + mi * 16 + (l >> 2);
        #pragma unroll
        for (int nj = 0; nj < 4; nj++) {
            int col = n0 + wn + nj * 8 + (l & 3) * 2;
            float bb1a = b1p[col], bb1b = b1p[col + 1];
            float bb2a = b2p[col], bb2b = b2p[col + 1];
            #pragma unroll
            for (int half = 0; half < 2; half++) {
                int r = r0 + half * 8;
                float g0 = c1[mi][nj][half * 2 + 0] + bb1a;
                float g1 = c1[mi][nj][half * 2 + 1] + bb1b;
                float v0 = c2[mi][nj][half * 2 + 0] + bb2a;
                float v1 = c2[mi][nj][half * 2 + 1] + bb2b;
                v0 *= 1.f / (1.f + __expf(-g0));
                v1 *= 1.f / (1.f + __expf(-g1));
                *(float2*)(Cf + (size_t)r * HID + col) = make_float2(v0, v1);
            }
        }
    }
}

// ================= attention v9: R13 structure + hoisted Q fragments =================
// smem bytes:
//   sQ  [0, 9216)                 : 64 x 72 fp16
//   stages 2 x 36864 [9216, 82944): per stage: K 128x72 + V 128x72
//   sE  [82944, 215040)           : 64 x 1032 fp16 (unnormalized e, for prob output)
//   sMask [215040, 219136)        : 1024 int
//   sInv  [219136, 219392)        : 64 float
//   sPart overlays stage region after main loop
#define EST 1032
#define KVST 72
#define CSTG 18432
#define ASTG 36864
#define ATTN_SMEM 219392

__global__ __launch_bounds__(512) void attn_mma(
    const __half* __restrict__ qf, const __half* __restrict__ kpf,
    const __half* __restrict__ vpf,
    const int* __restrict__ mask, float* __restrict__ attn_out,
    __half* __restrict__ xf)
{
    extern __shared__ char sab[];
    __half* sQ = (__half*)(sab);
    __half* sE = (__half*)(sab + 82944);
    int*   sMask = (int*)(sab + 215040);
    float* sInv  = (float*)(sab + 219136);
    float* sPart = (float*)(sab + 9216);

    const int tid = threadIdx.x, w = tid >> 5, l = tid & 31;
    const int q0 = blockIdx.x * 64, h = blockIdx.y, b = blockIdx.z;

    const uint32_t uQ  = smem_u32(sab);
    const uint32_t uK0 = uQ + 9216;

    // load Q tile (64 x 64 fp16) + mask
    {
        int r = tid >> 3, c8 = (tid & 7) * 8;
        size_t g = ((size_t)(b * SS + q0 + r)) * HID + h * HD + c8;
        *(uint4*)(sQ + r * KVST + c8) = *(const uint4*)(qf + g);
    }
    for (int k = tid; k < SS; k += 512) sMask[k] = mask[b * SS + k];

    const int mg = w & 3;           // 16-query row group
    const int sub = w >> 2;         // 32-key slice within 128-key chunk
    const int bRowL = (l >> 4) * 8 + (l & 7);
    const int bKofL = ((l >> 3) & 1) * 8;
    const uint32_t aLaneOff = (uint32_t)(((mg * 16 + (l & 15)) * KVST + (l >> 4) * 8) * 2);

    // issue one 128-key chunk (K + V) into stage st
    auto issueKV = [&](int chunk, int st) {
        const uint32_t dst = uK0 + (uint32_t)(st * ASTG);
        const int r0 = chunk * 128;
        #pragma unroll
        for (int i = 0; i < 2; i++) {
            int t = tid + i * 512;
            int row = t >> 3, c8 = (t & 7) * 8;
            uint32_t d = dst + (uint32_t)((row * KVST + c8) * 2);
            size_t g = ((size_t)(b * SS + r0 + row)) * HID + h * HD + c8;
            cp16(d,        kpf + g);
            cp16(d + CSTG, vpf + g);
        }
    };

    issueKV(0, 0); CP_COMMIT();

    // hoist Q fragments: loop-invariant across all chunks
    __syncthreads();
    uint32_t qfr[4][4];
    #pragma unroll
    for (int ks = 0; ks < 4; ks++)
        ldsm_x4(qfr[ks], uQ + aLaneOff + (uint32_t)(ks * 16 * 2));

    // x accumulator: 16q x 64d per warp (this warp's key slice)
    float xa[8][4];
    #pragma unroll
    for (int j = 0; j < 8; j++)
        #pragma unroll
        for (int q = 0; q < 4; q++) xa[j][q] = 0.f;

    // ---------- main loop: 8 chunks x 128 keys; QK -> exp -> (sE store + inline PV) ----------
    for (int ch = 0; ch < 8; ch++) {
        CP_WAIT0();
        __syncthreads();
        if (ch < 7) { issueKV(ch + 1, (ch + 1) & 1); CP_COMMIT(); }

        const uint32_t sbK = uK0 + (uint32_t)((ch & 1) * ASTG);
        const uint32_t sbV = sbK + CSTG;
        const int kw0 = ch * 128 + sub * 32;

        // --- QK^T for this warp's 16q x 32k slice ---
        float ea[2][2][4];
        #pragma unroll
        for (int p = 0; p < 2; p++)
            #pragma unroll
            for (int t = 0; t < 2; t++)
                #pragma unroll
                for (int q = 0; q < 4; q++) ea[p][t][q] = 0.f;

        #pragma unroll
        for (int ks = 0; ks < 4; ks++) {
            uint32_t bk[2][4];
            #pragma unroll
            for (int p = 0; p < 2; p++)
                ldsm_x4(bk[p], sbK + (uint32_t)(((sub * 32 + p * 16 + bRowL) * KVST + ks * 16 + bKofL) * 2));
            #pragma unroll
            for (int p = 0; p < 2; p++) {
                #pragma unroll
                for (int t = 0; t < 2; t++)
                    mma16816h(ea[p][t], qfr[ks], bk[p][t * 2], bk[p][t * 2 + 1]);
            }
        }

        // --- epilogue: mask + exp; store to sE and pack A-fragments for PV ---
        uint32_t aF[2][4];
        #pragma unroll
        for (int p = 0; p < 2; p++) {
            #pragma unroll
            for (int t = 0; t < 2; t++) {
                int kcol = kw0 + p * 16 + t * 8 + (l & 3) * 2;
                int mk0 = sMask[kcol], mk1 = sMask[kcol + 1];
                #pragma unroll
                for (int hf = 0; hf < 2; hf++) {
                    int row = mg * 16 + (l >> 2) + hf * 8;
                    float e0 = mk0 ? __expf(fminf(ea[p][t][hf * 2 + 0], 11.f)) : 0.f;
                    float e1 = mk1 ? __expf(fminf(ea[p][t][hf * 2 + 1], 11.f)) : 0.f;
                    __half2 h2 = __halves2half2(__float2half(e0), __float2half(e1));
                    *(__half2*)(sE + row * EST + kcol) = h2;
                    aF[p][t * 2 + hf] = *(uint32_t*)&h2;
                }
            }
        }

        // --- inline PV: xa += e_chunk @ V_chunk (16q x 32k x 64d) ---
        #pragma unroll
        for (int p = 0; p < 2; p++) {
            #pragma unroll
            for (int dt = 0; dt < 4; dt++) {
                uint32_t bv[4];
                ldsm_x4_t(bv, sbV + (uint32_t)(((sub * 32 + p * 16 + (l & 15)) * KVST + dt * 16 + (l >> 4) * 8) * 2));
                mma16816h(xa[dt * 2 + 0], aF[p], bv[0], bv[1]);
                mma16816h(xa[dt * 2 + 1], aF[p], bv[2], bv[3]);
            }
        }
    }
    __syncthreads();

    // ---------- Phase B: row sums + prob write ----------
    #pragma unroll
    for (int r = w * 4; r < w * 4 + 4; r++) {
        const __half* eh = sE + r * EST;
        uint32_t buf[16];
        float sum = 0.f;
        #pragma unroll
        for (int i = 0; i < 16; i++) {
            buf[i] = *(const uint32_t*)(eh + i * 64 + l * 2);
            __half2 v = *(__half2*)&buf[i];
            sum += __half2float(v.x) + __half2float(v.y);
        }
        #pragma unroll
        for (int o = 16; o > 0; o >>= 1) sum += __shfl_xor_sync(0xffffffffu, sum, o);
        float inv = 1.f / sum;
        if (l == 0) sInv[r] = inv;
        float* orow = attn_out + ((size_t)((b * NH + h) * SS + q0 + r)) * SS;
        #pragma unroll
        for (int i = 0; i < 16; i++) {
            __half2 v = *(__half2*)&buf[i];
            *(float2*)(orow + i * 64 + l * 2) =
                make_float2(__half2float(v.x) * inv, __half2float(v.y) * inv);
        }
    }
    __syncthreads();

    // ---------- x reduction over 4 key-slices (sub) via smem overlay ----------
    if (sub > 0) {
        float* dst = sPart + (sub - 1) * 4096;
        #pragma unroll
        for (int j = 0; j < 8; j++)
            #pragma unroll
            for (int v = 0; v < 4; v++) {
                int row = mg * 16 + (l >> 2) + (v >> 1) * 8;
                int col = (j >> 1) * 16 + (j & 1) * 8 + (l & 3) * 2 + (v & 1);
                dst[row * 64 + col] = xa[j][v];
            }
    }
    __syncthreads();
    if (sub == 0) {
        #pragma unroll
        for (int j = 0; j < 8; j++) {
            #pragma unroll
            for (int hf = 0; hf < 2; hf++) {
                int row = mg * 16 + (l >> 2) + hf * 8;
                int col = (j >> 1) * 16 + (j & 1) * 8 + (l & 3) * 2;
                float inv = sInv[row];
                float x0 = xa[j][hf * 2 + 0];
                float x1 = xa[j][hf * 2 + 1];
                #pragma unroll
                for (int p = 0; p < 3; p++) {
                    x0 += sPart[p * 4096 + row * 64 + col];
                    x1 += sPart[p * 4096 + row * 64 + col + 1];
                }
                x0 *= inv; x1 *= inv;
                size_t g = ((size_t)(b * SS + q0 + row)) * HID + h * HD + col;
                *(__half2*)(xf + g) = __halves2half2(__float2half(x0), __float2half(x1));
            }
        }
    }
}

// ================= launch =================
extern "C" void kernel_launch(void* const* d_in, const int* in_sizes, int n_in,
                              void* d_out, int out_size)
{
    const float* query = (const float*)d_in[0];
    const float* key_t = (const float*)d_in[1];
    const float* value = (const float*)d_in[2];
    const int*   mask  = (const int*)d_in[3];
    const float* Wq = (const float*)d_in[4];  const float* bq = (const float*)d_in[5];
    const float* Wk = (const float*)d_in[6];  const float* bk = (const float*)d_in[7];
    const float* Wv = (const float*)d_in[8];  const float* bv = (const float*)d_in[9];
    const float* Wo = (const float*)d_in[10]; const float* bo = (const float*)d_in[11];
    const float* W1 = (const float*)d_in[12]; const float* b1 = (const float*)d_in[13];
    const float* W2 = (const float*)d_in[14]; const float* b2 = (const float*)d_in[15];

    float* out       = (float*)d_out;
    float* out_gated = out;
    float* out_attn  = out + MH;

    __half *kf, *vf, *qfp, *kpf, *vpf, *xf, *cat, *wqk, *wfo, *wf;
    cudaGetSymbolAddress((void**)&kf, g_kf);
    cudaGetSymbolAddress((void**)&vf, g_vf);
    cudaGetSymbolAddress((void**)&qfp, g_qf);
    cudaGetSymbolAddress((void**)&kpf, g_kpf);
    cudaGetSymbolAddress((void**)&vpf, g_vpf);
    cudaGetSymbolAddress((void**)&xf, g_xf);
    cudaGetSymbolAddress((void**)&cat, g_cat);
    cudaGetSymbolAddress((void**)&wqk, g_wqk);
    cudaGetSymbolAddress((void**)&wfo, g_wfo);
    cudaGetSymbolAddress((void**)&wf, g_wf);

    size_t fsmem = (size_t)2 * FSTAGE * 2;   // 73728 B
    size_t esmem = (size_t)2 * E3STG * 2;    // 110592 B
    cudaFuncSetAttribute(gemm_qkv, cudaFuncAttributeMaxDynamicSharedMemorySize, (int)fsmem);
    cudaFuncSetAttribute(gemm_fp16, cudaFuncAttributeMaxDynamicSharedMemorySize, (int)fsmem);
    cudaFuncSetAttribute(gemm_ffn, cudaFuncAttributeMaxDynamicSharedMemorySize, (int)esmem);
    cudaFuncSetAttribute(attn_mma, cudaFuncAttributeMaxDynamicSharedMemorySize, ATTN_SMEM);

    const int actBlocks = (MROWS * HID / 4 + 255) / 256;
    dim3 wblk(32, 8);
    dim3 ggrid(HID / 128, MROWS / 128);      // (6, 64)

    // --- input conversions + weight splits ---
    conv3<<<dim3(actBlocks, 3), 256>>>(query, key_t, value, cat, kf, vf);
    split_wqk3<<<dim3(HID / 32, HID / 32, 3), wblk>>>(Wq, Wk, Wv, wqk);

    // --- QKV projections (fp16 single-term; Q pre-scaled 1/8) ---
    gemm_qkv<<<dim3(HID / 128, MROWS / 128, 3), 256, fsmem>>>(
        cat + HID, kf, vf, wqk, bq, bk, bv, qfp, kpf, vpf);

    // --- attention (flash-style inline PV, hoisted Q) ---
    attn_mma<<<dim3(SS / 64, NH, BB), 512, ATTN_SMEM>>>(
        qfp, kpf, vpf, mask, out_attn, xf);

    // --- Wo (fp16) -> cat[:, 0:768] ---
    split_w_fp16<<<dim3(HID / 32, HID / 32), wblk>>>(Wo, HID, HID, wfo);
    gemm_fp16<<<ggrid, 256, fsmem>>>(
        xf, HID, wfo, HID, bo, cat, 2 * HID);

    // --- fused FFN (fp16, K=1536): out = sigmoid(cat@W1+b1) * (cat@W2+b2) ---
    split_wf2<<<dim3(HID / 32, 2 * HID / 32, 2), wblk>>>(W1, W2, wf);
    gemm_ffn<<<ggrid, 256, esmem>>>(
        cat, wf, wf + (size_t)2 * HID * HID, b1, b2, out_gated);
}

// round 17
// speedup vs baseline: 1.1673x; 1.0228x over previous
#include <cuda_runtime.h>
#include <cuda_fp16.h>
#include <math.h>
#include <stdint.h>

#define BB 8
#define SS 1024
#define HID 768
#define NH 12
#define HD 64
#define MROWS (BB*SS)   // 8192
#define MH ((size_t)MROWS*HID)

// ---------------- scratch (device globals; no allocation allowed) ----------------
__device__ __align__(256) __half g_kf [MH];                     // raw key fp16
__device__ __align__(256) __half g_vf [MH];                     // raw value fp16
__device__ __align__(256) __half g_qf [MH];                     // projected Q (fp16, prescaled)
__device__ __align__(256) __half g_kpf[MH];                     // projected K (fp16)
__device__ __align__(256) __half g_vpf[MH];                     // projected V (fp16)

__device__ __align__(256) __half g_xf [MH];
__device__ __align__(256) __half g_cat[2*MH];
__device__ __align__(256) __half g_wqk[(size_t)3*HID*HID];      // Wq,Wk,Wv fp16 [N][K]
__device__ __align__(256) __half g_wfo[(size_t)HID*HID];
__device__ __align__(256) __half g_wf [(size_t)2*2*HID*HID];    // W1,W2 fp16 [N][K]

// ================= helpers =================
__device__ __forceinline__ uint32_t smem_u32(const void* p) {
    uint32_t a;
    asm("{ .reg .u64 t; cvta.to.shared.u64 t, %1; cvt.u32.u64 %0, t; }" : "=r"(a) : "l"(p));
    return a;
}
__device__ __forceinline__ void ldsm_x4(uint32_t* r, uint32_t addr) {
    asm volatile("ldmatrix.sync.aligned.m8n8.x4.shared.b16 {%0,%1,%2,%3}, [%4];"
                 : "=r"(r[0]), "=r"(r[1]), "=r"(r[2]), "=r"(r[3]) : "r"(addr));
}
__device__ __forceinline__ void ldsm_x4_t(uint32_t* r, uint32_t addr) {
    asm volatile("ldmatrix.sync.aligned.m8n8.x4.trans.shared.b16 {%0,%1,%2,%3}, [%4];"
                 : "=r"(r[0]), "=r"(r[1]), "=r"(r[2]), "=r"(r[3]) : "r"(addr));
}
__device__ __forceinline__ void mma16816h(float* c, const uint32_t* a, uint32_t b0, uint32_t b1) {
    asm volatile("mma.sync.aligned.m16n8k16.row.col.f32.f16.f16.f32 "
                 "{%0,%1,%2,%3}, {%4,%5,%6,%7}, {%8,%9}, {%0,%1,%2,%3};"
                 : "+f"(c[0]), "+f"(c[1]), "+f"(c[2]), "+f"(c[3])
                 : "r"(a[0]), "r"(a[1]), "r"(a[2]), "r"(a[3]), "r"(b0), "r"(b1));
}
__device__ __forceinline__ void cp16(uint32_t dst, const void* src) {
    asm volatile("cp.async.cg.shared.global [%0], [%1], 16;" :: "r"(dst), "l"(src));
}
#define CP_COMMIT() asm volatile("cp.async.commit_group;" ::: "memory")
#define CP_WAIT0()  asm volatile("cp.async.wait_group 0;" ::: "memory")

// ================= merged prep kernel =================
// flat grid: [0, 3*ACTB)                -> fp32->fp16 conversions (query->cat, key->kf, value->vf)
//            [3*ACTB, 3*ACTB+4*576)     -> Wq/Wk/Wv/Wo transpose-splits (768x768)
//            [.., +2*1152)              -> W1/W2 transpose-splits (1536x768)
#define ACTB (MROWS * HID / 4 / 256)    // 6144

__global__ __launch_bounds__(256) void prep(
    const float* __restrict__ q, const float* __restrict__ k, const float* __restrict__ v,
    const float* __restrict__ Wq, const float* __restrict__ Wk, const float* __restrict__ Wv,
    const float* __restrict__ Wo, const float* __restrict__ W1, const float* __restrict__ W2,
    __half* __restrict__ cat, __half* __restrict__ kf, __half* __restrict__ vf,
    __half* __restrict__ wqk, __half* __restrict__ wfo, __half* __restrict__ wf)
{
    __shared__ float t[32][33];
    const int tid = threadIdx.x;
    int bx = blockIdx.x;

    if (bx < 3 * ACTB) {
        const int z = bx / ACTB;
        const float* src = (z == 0) ? q : (z == 1) ? k : v;
        size_t e = ((size_t)(bx % ACTB) * 256 + tid) * 4;
        int m = (int)(e / HID), c = (int)(e % HID);
        float4 x = *(const float4*)(src + e);
        __half* dst = (z == 0) ? (cat + (size_t)m * (2 * HID) + HID + c)
                    : (z == 1) ? (kf + e) : (vf + e);
        *(__half2*)(dst)     = __halves2half2(__float2half(x.x), __float2half(x.y));
        *(__half2*)(dst + 2) = __halves2half2(__float2half(x.z), __float2half(x.w));
        return;
    }
    bx -= 3 * ACTB;
    const int tx = tid & 31, ty = tid >> 5;

    if (bx < 4 * 576) {
        const int z = bx / 576;
        int r = bx % 576;
        int n0 = (r % 24) * 32, k0 = (r / 24) * 32;
        const float* W = (z == 0) ? Wq : (z == 1) ? Wk : (z == 2) ? Wv : Wo;
        __half* O = (z < 3) ? (wqk + (size_t)z * HID * HID) : wfo;
        for (int j = ty; j < 32; j += 8)
            t[j][tx] = W[(size_t)(k0 + j) * HID + n0 + tx];
        __syncthreads();
        for (int j = ty; j < 32; j += 8)
            O[(size_t)(n0 + j) * HID + k0 + tx] = __float2half(t[tx][j]);
        return;
    }
    bx -= 4 * 576;
    {
        const int z = bx / 1152;
        int r = bx % 1152;
        int n0 = (r % 24) * 32, k0 = (r / 24) * 32;   // k0 in [0,1536)
        const float* W = z ? W2 : W1;
        __half* O = wf + (size_t)z * 2 * HID * HID;
        for (int j = ty; j < 32; j += 8)
            t[j][tx] = W[(size_t)(k0 + j) * HID + n0 + tx];
        __syncthreads();
        for (int j = ty; j < 32; j += 8)
            O[(size_t)(n0 + j) * (2 * HID) + k0 + tx] = __float2half(t[tx][j]);
    }
}

// ================= fp16 QKV projection GEMM (batched z = 0,1,2) =================
#define GSTRIDE 72
#define GBUF (128 * GSTRIDE)
#define FSTAGE (2 * GBUF)

__global__ __launch_bounds__(256) void gemm_qkv(
    const __half* __restrict__ Aq, const __half* __restrict__ Ak,
    const __half* __restrict__ Av, const __half* __restrict__ Bw,
    const float* __restrict__ bq, const float* __restrict__ bk,
    const float* __restrict__ bv,
    __half* __restrict__ oq, __half* __restrict__ ok, __half* __restrict__ ov)
{
    extern __shared__ __half smh[];
    const int tid = threadIdx.x;
    const int w = tid >> 5, l = tid & 31;
    const int z = blockIdx.z;
    const int m0 = blockIdx.y * 128;
    const int n0 = blockIdx.x * 128;
    const int wm = (w >> 2) * 64;
    const int wn = (w & 3) * 32;

    const __half* A = (z == 0) ? Aq : (z == 1) ? Ak : Av;
    const int lda = (z == 0) ? 2 * HID : HID;
    const __half* B = Bw + (size_t)z * HID * HID;
    const float* bias = (z == 0) ? bq : (z == 1) ? bk : bv;
    const float scale = (z == 0) ? 0.125f : 1.f;
    __half* out = (z == 0) ? oq : (z == 1) ? ok : ov;

    float c[4][4][4];
    #pragma unroll
    for (int i = 0; i < 4; i++)
        #pragma unroll
        for (int j = 0; j < 4; j++)
            #pragma unroll
            for (int q = 0; q < 4; q++) c[i][j][q] = 0.f;

    const uint32_t sbase = smem_u32(smh);
    const int aRow = wm + (l & 15), aKof = (l >> 4) * 8;
    const int bRow = wn + (l >> 4) * 8 + (l & 7), bKof = ((l >> 3) & 1) * 8;
    const int nChunks = HID >> 6;

    auto issue = [&](int ch) {
        const uint32_t dstBase = sbase + (uint32_t)((ch & 1) * FSTAGE * 2);
        const int k0 = ch << 6;
        #pragma unroll
        for (int i = 0; i < 4; i++) {
            int t = tid + i * 256;
            int row = t >> 3, c8 = (t & 7) * 8;
            uint32_t d = dstBase + (uint32_t)((row * GSTRIDE + c8) * 2);
            cp16(d,            A + (size_t)(m0 + row) * lda + k0 + c8);
            cp16(d + GBUF * 2, B + (size_t)(n0 + row) * HID + k0 + c8);
        }
    };

    issue(0); CP_COMMIT();
    for (int ch = 0; ch < nChunks; ch++) {
        CP_WAIT0();
        __syncthreads();
        if (ch + 1 < nChunks) { issue(ch + 1); CP_COMMIT(); }

        const uint32_t sb = sbase + (uint32_t)((ch & 1) * FSTAGE * 2);
        const uint32_t aB = sb + (uint32_t)((aRow * GSTRIDE + aKof) * 2);
        const uint32_t bB = sb + GBUF * 2 + (uint32_t)((bRow * GSTRIDE + bKof) * 2);

        #pragma unroll
        for (int ks = 0; ks < 4; ks++) {
            const uint32_t kb = (uint32_t)(ks * 16 * 2);
            uint32_t ah[4][4], bh[2][4];
            #pragma unroll
            for (int mi = 0; mi < 4; mi++)
                ldsm_x4(ah[mi], aB + (uint32_t)(mi * 16 * GSTRIDE * 2) + kb);
            #pragma unroll
            for (int p = 0; p < 2; p++)
                ldsm_x4(bh[p], bB + (uint32_t)(p * 16 * GSTRIDE * 2) + kb);
            #pragma unroll
            for (int mi = 0; mi < 4; mi++) {
                #pragma unroll
                for (int nj = 0; nj < 4; nj++) {
                    const int p = nj >> 1, s = (nj & 1) * 2;
                    mma16816h(c[mi][nj], ah[mi], bh[p][s], bh[p][s + 1]);
                }
            }
        }
        __syncthreads();
    }

    #pragma unroll
    for (int mi = 0; mi < 4; mi++) {
        int r0 = m0 + wm + mi * 16 + (l >> 2);
        #pragma unroll
        for (int nj = 0; nj < 4; nj++) {
            int col = n0 + wn + nj * 8 + (l & 3) * 2;
            float b0 = bias[col], b1 = bias[col + 1];
            #pragma unroll
            for (int half = 0; half < 2; half++) {
                int r = r0 + half * 8;
                float v0 = (c[mi][nj][half * 2 + 0] + b0) * scale;
                float v1 = (c[mi][nj][half * 2 + 1] + b1) * scale;
                *(__half2*)(out + (size_t)r * HID + col) =
                    __halves2half2(__float2half(v0), __float2half(v1));
            }
        }
    }
}

// ================= fp16 single-term GEMM (Wo) =================
__global__ __launch_bounds__(256) void gemm_fp16(
    const __half* __restrict__ A, int lda, const __half* __restrict__ B,
    int Kdim, const float* __restrict__ bias,
    __half* __restrict__ Ch, int ldch)
{
    extern __shared__ __half smh[];
    const int tid = threadIdx.x;
    const int w = tid >> 5, l = tid & 31;
    const int m0 = blockIdx.y * 128;
    const int n0 = blockIdx.x * 128;
    const int wm = (w >> 2) * 64;
    const int wn = (w & 3) * 32;

    float c[4][4][4];
    #pragma unroll
    for (int i = 0; i < 4; i++)
        #pragma unroll
        for (int j = 0; j < 4; j++)
            #pragma unroll
            for (int q = 0; q < 4; q++) c[i][j][q] = 0.f;

    const uint32_t sbase = smem_u32(smh);
    const int aRow = wm + (l & 15), aKof = (l >> 4) * 8;
    const int bRow = wn + (l >> 4) * 8 + (l & 7), bKof = ((l >> 3) & 1) * 8;
    const int nChunks = Kdim >> 6;

    auto issue = [&](int ch) {
        const uint32_t dstBase = sbase + (uint32_t)((ch & 1) * FSTAGE * 2);
        const int k0 = ch << 6;
        #pragma unroll
        for (int i = 0; i < 4; i++) {
            int t = tid + i * 256;
            int row = t >> 3, c8 = (t & 7) * 8;
            uint32_t d = dstBase + (uint32_t)((row * GSTRIDE + c8) * 2);
            cp16(d,            A + (size_t)(m0 + row) * lda  + k0 + c8);
            cp16(d + GBUF * 2, B + (size_t)(n0 + row) * Kdim + k0 + c8);
        }
    };

    issue(0); CP_COMMIT();
    for (int ch = 0; ch < nChunks; ch++) {
        CP_WAIT0();
        __syncthreads();
        if (ch + 1 < nChunks) { issue(ch + 1); CP_COMMIT(); }

        const uint32_t sb = sbase + (uint32_t)((ch & 1) * FSTAGE * 2);
        const uint32_t aB = sb + (uint32_t)((aRow * GSTRIDE + aKof) * 2);
        const uint32_t bB = sb + GBUF * 2 + (uint32_t)((bRow * GSTRIDE + bKof) * 2);

        #pragma unroll
        for (int ks = 0; ks < 4; ks++) {
            const uint32_t kb = (uint32_t)(ks * 16 * 2);
            uint32_t ah[4][4], bh[2][4];
            #pragma unroll
            for (int mi = 0; mi < 4; mi++)
                ldsm_x4(ah[mi], aB + (uint32_t)(mi * 16 * GSTRIDE * 2) + kb);
            #pragma unroll
            for (int p = 0; p < 2; p++)
                ldsm_x4(bh[p], bB + (uint32_t)(p * 16 * GSTRIDE * 2) + kb);
            #pragma unroll
            for (int mi = 0; mi < 4; mi++) {
                #pragma unroll
                for (int nj = 0; nj < 4; nj++) {
                    const int p = nj >> 1, s = (nj & 1) * 2;
                    mma16816h(c[mi][nj], ah[mi], bh[p][s], bh[p][s + 1]);
                }
            }
        }
        __syncthreads();
    }

    #pragma unroll
    for (int mi = 0; mi < 4; mi++) {
        int r0 = m0 + wm + mi * 16 + (l >> 2);
        #pragma unroll
        for (int nj = 0; nj < 4; nj++) {
            int col = n0 + wn + nj * 8 + (l & 3) * 2;
            float b0 = bias[col], b1 = bias[col + 1];
            #pragma unroll
            for (int half = 0; half < 2; half++) {
                int r = r0 + half * 8;
                float v0 = c[mi][nj][half * 2 + 0] + b0;
                float v1 = c[mi][nj][half * 2 + 1] + b1;
                *(__half2*)(Ch + (size_t)r * ldch + col) =
                    __halves2half2(__float2half(v0), __float2half(v1));
            }
        }
    }
}

// ================= fused FFN: out = sigmoid(cat@W1+b1) * (cat@W2+b2) =================
#define E3STG (3 * GBUF)

__global__ __launch_bounds__(256) void gemm_ffn(
    const __half* __restrict__ A, const __half* __restrict__ B1,
    const __half* __restrict__ B2,
    const float* __restrict__ b1p, const float* __restrict__ b2p,
    float* __restrict__ Cf)
{
    extern __shared__ __half smh[];
    const int tid = threadIdx.x;
    const int w = tid >> 5, l = tid & 31;
    const int m0 = blockIdx.y * 128;
    const int n0 = blockIdx.x * 128;
    const int wm = (w >> 2) * 64;
    const int wn = (w & 3) * 32;
    const int Kdim = 2 * HID;

    float c1[4][4][4], c2[4][4][4];
    #pragma unroll
    for (int i = 0; i < 4; i++)
        #pragma unroll
        for (int j = 0; j < 4; j++)
            #pragma unroll
            for (int q = 0; q < 4; q++) { c1[i][j][q] = 0.f; c2[i][j][q] = 0.f; }

    const uint32_t sbase = smem_u32(smh);
    const int aRow = wm + (l & 15), aKof = (l >> 4) * 8;
    const int bRow = wn + (l >> 4) * 8 + (l & 7), bKof = ((l >> 3) & 1) * 8;
    const int nChunks = Kdim >> 6;   // 24

    auto issue = [&](int ch) {
        const uint32_t dstBase = sbase + (uint32_t)((ch & 1) * E3STG * 2);
        const int k0 = ch << 6;
        #pragma unroll
        for (int i = 0; i < 4; i++) {
            int t = tid + i * 256;
            int row = t >> 3, c8 = (t & 7) * 8;
            uint32_t d = dstBase + (uint32_t)((row * GSTRIDE + c8) * 2);
            cp16(d,                A  + (size_t)(m0 + row) * Kdim + k0 + c8);
            cp16(d + GBUF * 2,     B1 + (size_t)(n0 + row) * Kdim + k0 + c8);
            cp16(d + 2 * GBUF * 2, B2 + (size_t)(n0 + row) * Kdim + k0 + c8);
        }
    };

    issue(0); CP_COMMIT();
    for (int ch = 0; ch < nChunks; ch++) {
        CP_WAIT0();
        __syncthreads();
        if (ch + 1 < nChunks) { issue(ch + 1); CP_COMMIT(); }

        const uint32_t sb = sbase + (uint32_t)((ch & 1) * E3STG * 2);
        const uint32_t aB  = sb + (uint32_t)((aRow * GSTRIDE + aKof) * 2);
        const uint32_t b1B = sb + GBUF * 2 + (uint32_t)((bRow * GSTRIDE + bKof) * 2);
        const uint32_t b2B = b1B + GBUF * 2;

        #pragma unroll
        for (int ks = 0; ks < 4; ks++) {
            const uint32_t kb = (uint32_t)(ks * 16 * 2);
            uint32_t ah[4][4], bh1[2][4], bh2[2][4];
            #pragma unroll
            for (int mi = 0; mi < 4; mi++)
                ldsm_x4(ah[mi], aB + (uint32_t)(mi * 16 * GSTRIDE * 2) + kb);
            #pragma unroll
            for (int p = 0; p < 2; p++) {
                ldsm_x4(bh1[p], b1B + (uint32_t)(p * 16 * GSTRIDE * 2) + kb);
                ldsm_x4(bh2[p], b2B + (uint32_t)(p * 16 * GSTRIDE * 2) + kb);
            }
            #pragma unroll
            for (int mi = 0; mi < 4; mi++) {
                #pragma unroll
                for (int nj = 0; nj < 4; nj++) {
                    const int p = nj >> 1, s = (nj & 1) * 2;
                    mma16816h(c1[mi][nj], ah[mi], bh1[p][s], bh1[p][s + 1]);
                    mma16816h(c2[mi][nj], ah[mi], bh2[p][s], bh2[p][s + 1]);
                }
            }
        }
        __syncthreads();
    }

    #pragma unroll
    for (int mi = 0; mi < 4; mi++) {
        int r0 = m0 + wm + mi * 16 + (l >> 2);
        #pragma unroll
        for (int nj = 0; nj < 4; nj++) {
            int col = n0 + wn + nj * 8 + (l & 3) * 2;
            float bb1a = b1p[col], bb1b = b1p[col + 1];
            float bb2a = b2p[col], bb2b = b2p[col + 1];
            #pragma unroll
            for (int half = 0; half < 2; half++) {
                int r = r0 + half * 8;
                float g0 = c1[mi][nj][half * 2 + 0] + bb1a;
                float g1 = c1[mi][nj][half * 2 + 1] + bb1b;
                float v0 = c2[mi][nj][half * 2 + 0] + bb2a;
                float v1 = c2[mi][nj][half * 2 + 1] + bb2b;
                v0 *= 1.f / (1.f + __expf(-g0));
                v1 *= 1.f / (1.f + __expf(-g1));
                *(float2*)(Cf + (size_t)r * HID + col) = make_float2(v0, v1);
            }
        }
    }
}

// ================= attention v10: R16 + f4 prob stores =================
#define EST 1032
#define KVST 72
#define CSTG 18432
#define ASTG 36864
#define ATTN_SMEM 219392

__global__ __launch_bounds__(512) void attn_mma(
    const __half* __restrict__ qf, const __half* __restrict__ kpf,
    const __half* __restrict__ vpf,
    const int* __restrict__ mask, float* __restrict__ attn_out,
    __half* __restrict__ xf)
{
    extern __shared__ char sab[];
    __half* sQ = (__half*)(sab);
    __half* sE = (__half*)(sab + 82944);
    int*   sMask = (int*)(sab + 215040);
    float* sInv  = (float*)(sab + 219136);
    float* sPart = (float*)(sab + 9216);

    const int tid = threadIdx.x, w = tid >> 5, l = tid & 31;
    const int q0 = blockIdx.x * 64, h = blockIdx.y, b = blockIdx.z;

    const uint32_t uQ  = smem_u32(sab);
    const uint32_t uK0 = uQ + 9216;

    // load Q tile (64 x 64 fp16) + mask
    {
        int r = tid >> 3, c8 = (tid & 7) * 8;
        size_t g = ((size_t)(b * SS + q0 + r)) * HID + h * HD + c8;
        *(uint4*)(sQ + r * KVST + c8) = *(const uint4*)(qf + g);
    }
    for (int k = tid; k < SS; k += 512) sMask[k] = mask[b * SS + k];

    const int mg = w & 3;
    const int sub = w >> 2;
    const int bRowL = (l >> 4) * 8 + (l & 7);
    const int bKofL = ((l >> 3) & 1) * 8;
    const uint32_t aLaneOff = (uint32_t)(((mg * 16 + (l & 15)) * KVST + (l >> 4) * 8) * 2);

    auto issueKV = [&](int chunk, int st) {
        const uint32_t dst = uK0 + (uint32_t)(st * ASTG);
        const int r0 = chunk * 128;
        #pragma unroll
        for (int i = 0; i < 2; i++) {
            int t = tid + i * 512;
            int row = t >> 3, c8 = (t & 7) * 8;
            uint32_t d = dst + (uint32_t)((row * KVST + c8) * 2);
            size_t g = ((size_t)(b * SS + r0 + row)) * HID + h * HD + c8;
            cp16(d,        kpf + g);
            cp16(d + CSTG, vpf + g);
        }
    };

    issueKV(0, 0); CP_COMMIT();

    // hoisted Q fragments
    __syncthreads();
    uint32_t qfr[4][4];
    #pragma unroll
    for (int ks = 0; ks < 4; ks++)
        ldsm_x4(qfr[ks], uQ + aLaneOff + (uint32_t)(ks * 16 * 2));

    float xa[8][4];
    #pragma unroll
    for (int j = 0; j < 8; j++)
        #pragma unroll
        for (int q = 0; q < 4; q++) xa[j][q] = 0.f;

    // ---------- main loop ----------
    for (int ch = 0; ch < 8; ch++) {
        CP_WAIT0();
        __syncthreads();
        if (ch < 7) { issueKV(ch + 1, (ch + 1) & 1); CP_COMMIT(); }

        const uint32_t sbK = uK0 + (uint32_t)((ch & 1) * ASTG);
        const uint32_t sbV = sbK + CSTG;
        const int kw0 = ch * 128 + sub * 32;

        float ea[2][2][4];
        #pragma unroll
        for (int p = 0; p < 2; p++)
            #pragma unroll
            for (int t = 0; t < 2; t++)
                #pragma unroll
                for (int q = 0; q < 4; q++) ea[p][t][q] = 0.f;

        #pragma unroll
        for (int ks = 0; ks < 4; ks++) {
            uint32_t bk[2][4];
            #pragma unroll
            for (int p = 0; p < 2; p++)
                ldsm_x4(bk[p], sbK + (uint32_t)(((sub * 32 + p * 16 + bRowL) * KVST + ks * 16 + bKofL) * 2));
            #pragma unroll
            for (int p = 0; p < 2; p++) {
                #pragma unroll
                for (int t = 0; t < 2; t++)
                    mma16816h(ea[p][t], qfr[ks], bk[p][t * 2], bk[p][t * 2 + 1]);
            }
        }

        uint32_t aF[2][4];
        #pragma unroll
        for (int p = 0; p < 2; p++) {
            #pragma unroll
            for (int t = 0; t < 2; t++) {
                int kcol = kw0 + p * 16 + t * 8 + (l & 3) * 2;
                int mk0 = sMask[kcol], mk1 = sMask[kcol + 1];
                #pragma unroll
                for (int hf = 0; hf < 2; hf++) {
                    int row = mg * 16 + (l >> 2) + hf * 8;
                    float e0 = mk0 ? __expf(fminf(ea[p][t][hf * 2 + 0], 11.f)) : 0.f;
                    float e1 = mk1 ? __expf(fminf(ea[p][t][hf * 2 + 1], 11.f)) : 0.f;
                    __half2 h2 = __halves2half2(__float2half(e0), __float2half(e1));
                    *(__half2*)(sE + row * EST + kcol) = h2;
                    aF[p][t * 2 + hf] = *(uint32_t*)&h2;
                }
            }
        }

        #pragma unroll
        for (int p = 0; p < 2; p++) {
            #pragma unroll
            for (int dt = 0; dt < 4; dt++) {
                uint32_t bv[4];
                ldsm_x4_t(bv, sbV + (uint32_t)(((sub * 32 + p * 16 + (l & 15)) * KVST + dt * 16 + (l >> 4) * 8) * 2));
                mma16816h(xa[dt * 2 + 0], aF[p], bv[0], bv[1]);
                mma16816h(xa[dt * 2 + 1], aF[p], bv[2], bv[3]);
            }
        }
    }
    __syncthreads();

    // ---------- Phase B: row sums + prob write (f4 stores) ----------
    {
        float* obase = attn_out + ((size_t)((b * NH + h) * SS + q0)) * SS;
        #pragma unroll
        for (int r = w * 4; r < w * 4 + 4; r++) {
            const __half* eh = sE + r * EST + l * 4;
            uint2 buf[8];
            float sum = 0.f;
            #pragma unroll
            for (int i = 0; i < 8; i++) {
                buf[i] = *(const uint2*)(eh + i * 128);
                __half2 a = *(__half2*)&buf[i].x;
                __half2 bb = *(__half2*)&buf[i].y;
                sum += (__half2float(a.x) + __half2float(a.y))
                     + (__half2float(bb.x) + __half2float(bb.y));
            }
            #pragma unroll
            for (int o = 16; o > 0; o >>= 1) sum += __shfl_xor_sync(0xffffffffu, sum, o);
            float inv = 1.f / sum;
            if (l == 0) sInv[r] = inv;
            float* orow = obase + (size_t)r * SS + l * 4;
            #pragma unroll
            for (int i = 0; i < 8; i++) {
                __half2 a = *(__half2*)&buf[i].x;
                __half2 bb = *(__half2*)&buf[i].y;
                float4 v = make_float4(__half2float(a.x) * inv, __half2float(a.y) * inv,
                                       __half2float(bb.x) * inv, __half2float(bb.y) * inv);
                *(float4*)(orow + i * 128) = v;
            }
        }
    }
    __syncthreads();

    // ---------- x reduction over 4 key-slices (sub) via smem overlay ----------
    if (sub > 0) {
        float* dst = sPart + (sub - 1) * 4096;
        #pragma unroll
        for (int j = 0; j < 8; j++)
            #pragma unroll
            for (int v = 0; v < 4; v++) {
                int row = mg * 16 + (l >> 2) + (v >> 1) * 8;
                int col = (j >> 1) * 16 + (j & 1) * 8 + (l & 3) * 2 + (v & 1);
                dst[row * 64 + col] = xa[j][v];
            }
    }
    __syncthreads();
    if (sub == 0) {
        #pragma unroll
        for (int j = 0; j < 8; j++) {
            #pragma unroll
            for (int hf = 0; hf < 2; hf++) {
                int row = mg * 16 + (l >> 2) + hf * 8;
                int col = (j >> 1) * 16 + (j & 1) * 8 + (l & 3) * 2;
                float inv = sInv[row];
                float x0 = xa[j][hf * 2 + 0];
                float x1 = xa[j][hf * 2 + 1];
                #pragma unroll
                for (int p = 0; p < 3; p++) {
                    x0 += sPart[p * 4096 + row * 64 + col];
                    x1 += sPart[p * 4096 + row * 64 + col + 1];
                }
                x0 *= inv; x1 *= inv;
                size_t g = ((size_t)(b * SS + q0 + row)) * HID + h * HD + col;
                *(__half2*)(xf + g) = __halves2half2(__float2half(x0), __float2half(x1));
            }
        }
    }
}

// ================= launch =================
extern "C" void kernel_launch(void* const* d_in, const int* in_sizes, int n_in,
                              void* d_out, int out_size)
{
    const float* query = (const float*)d_in[0];
    const float* key_t = (const float*)d_in[1];
    const float* value = (const float*)d_in[2];
    const int*   mask  = (const int*)d_in[3];
    const float* Wq = (const float*)d_in[4];  const float* bq = (const float*)d_in[5];
    const float* Wk = (const float*)d_in[6];  const float* bk = (const float*)d_in[7];
    const float* Wv = (const float*)d_in[8];  const float* bv = (const float*)d_in[9];
    const float* Wo = (const float*)d_in[10]; const float* bo = (const float*)d_in[11];
    const float* W1 = (const float*)d_in[12]; const float* b1 = (const float*)d_in[13];
    const float* W2 = (const float*)d_in[14]; const float* b2 = (const float*)d_in[15];

    float* out       = (float*)d_out;
    float* out_gated = out;
    float* out_attn  = out + MH;

    __half *kf, *vf, *qfp, *kpf, *vpf, *xf, *cat, *wqk, *wfo, *wf;
    cudaGetSymbolAddress((void**)&kf, g_kf);
    cudaGetSymbolAddress((void**)&vf, g_vf);
    cudaGetSymbolAddress((void**)&qfp, g_qf);
    cudaGetSymbolAddress((void**)&kpf, g_kpf);
    cudaGetSymbolAddress((void**)&vpf, g_vpf);
    cudaGetSymbolAddress((void**)&xf, g_xf);
    cudaGetSymbolAddress((void**)&cat, g_cat);
    cudaGetSymbolAddress((void**)&wqk, g_wqk);
    cudaGetSymbolAddress((void**)&wfo, g_wfo);
    cudaGetSymbolAddress((void**)&wf, g_wf);

    size_t fsmem = (size_t)2 * FSTAGE * 2;   // 73728 B
    size_t esmem = (size_t)2 * E3STG * 2;    // 110592 B
    cudaFuncSetAttribute(gemm_qkv, cudaFuncAttributeMaxDynamicSharedMemorySize, (int)fsmem);
    cudaFuncSetAttribute(gemm_fp16, cudaFuncAttributeMaxDynamicSharedMemorySize, (int)fsmem);
    cudaFuncSetAttribute(gemm_ffn, cudaFuncAttributeMaxDynamicSharedMemorySize, (int)esmem);
    cudaFuncSetAttribute(attn_mma, cudaFuncAttributeMaxDynamicSharedMemorySize, ATTN_SMEM);

    dim3 ggrid(HID / 128, MROWS / 128);      // (6, 64)

    // --- merged prep: conversions + ALL weight splits (off the critical path) ---
    prep<<<3 * ACTB + 4 * 576 + 2 * 1152, 256>>>(
        query, key_t, value, Wq, Wk, Wv, Wo, W1, W2,
        cat, kf, vf, wqk, wfo, wf);

    // --- QKV projections (fp16 single-term; Q pre-scaled 1/8) ---
    gemm_qkv<<<dim3(HID / 128, MROWS / 128, 3), 256, fsmem>>>(
        cat + HID, kf, vf, wqk, bq, bk, bv, qfp, kpf, vpf);

    // --- attention (flash-style inline PV, hoisted Q, f4 prob stores) ---
    attn_mma<<<dim3(SS / 64, NH, BB), 512, ATTN_SMEM>>>(
        qfp, kpf, vpf, mask, out_attn, xf);

    // --- Wo (fp16) -> cat[:, 0:768] ---
    gemm_fp16<<<ggrid, 256, fsmem>>>(
        xf, HID, wfo, HID, bo, cat, 2 * HID);

    // --- fused FFN (fp16, K=1536): out = sigmoid(cat@W1+b1) * (cat@W2+b2) ---
    gemm_ffn<<<ggrid, 256, esmem>>>(
        cat, wf, wf + (size_t)2 * HID * HID, b1, b2, out_gated);
}